// round 1
// baseline (speedup 1.0000x reference)
#include <cuda_runtime.h>
#include <cuda_bf16.h>
#include <math.h>

// Problem dims
#define LY  4
#define BN  4
#define TT_ 1024   // T
#define TCC 1024   // TC
#define T1_ 2048   // T1
#define DD  384    // D
#define DKK 256    // DK
#define FFF 1536   // FF
#define TTMIX 0.1f
#define LN_EPS 1e-5f

// ---------------- scratch (device globals; allocation-guard safe) -------------
__device__ __align__(128) float g_x  [BN * TT_ * DD];
__device__ __align__(128) float g_q  [BN * TT_ * DD];
__device__ __align__(128) float g_k  [BN * T1_ * DD];
__device__ __align__(128) float g_v  [BN * T1_ * DD];
__device__ __align__(128) float g_att[(long long)BN * TT_ * T1_];
__device__ __align__(128) float g_unk[BN * TT_ * DD];
__device__ __align__(128) float g_kno[BN * TCC * DD];
__device__ __align__(128) float g_s1 [(long long)BN * TT_ * TCC];
__device__ __align__(128) float g_mix[(long long)BN * TT_ * T1_];
__device__ __align__(128) float g_z  [BN * TT_ * DD];
__device__ __align__(128) float g_h  [BN * TT_ * FFF];

// ---------------- SGEMM: C = alpha * A @ op(B) (+bias) (+relu) ----------------
// A: [M,K] row-major. TB=1: B is [N,K] row-major (C = A B^T). TB=0: B is [K,N].
// 64x64 tile, BK=16, 256 threads, 4x4 microtile per thread. Batched via blockIdx.z.
template<int TB>
__global__ void __launch_bounds__(256)
sgemm_kernel(const float* __restrict__ A, const float* __restrict__ Bm,
             const float* __restrict__ bias, float* __restrict__ C,
             int M, int N, int K, float alpha, int relu,
             long long sA, long long sB, long long sC)
{
    __shared__ float As[16][65];
    __shared__ float Bs[16][65];

    const float* Ab = A  + (long long)blockIdx.z * sA;
    const float* Bb = Bm + (long long)blockIdx.z * sB;
    float*       Cb = C  + (long long)blockIdx.z * sC;

    const int tid = threadIdx.x;
    const int tx  = tid & 15;       // 0..15  -> n
    const int ty  = tid >> 4;       // 0..15  -> m
    const int bm0 = blockIdx.y * 64;
    const int bn0 = blockIdx.x * 64;

    float acc[4][4] = {};

    for (int k0 = 0; k0 < K; k0 += 16) {
        // A tile load: 64x16 via float4 (each thread: one float4)
        {
            int m  = tid >> 2;            // 0..63
            int kq = (tid & 3) * 4;       // 0,4,8,12
            float4 a4 = *reinterpret_cast<const float4*>(
                &Ab[(long long)(bm0 + m) * K + k0 + kq]);
            As[kq+0][m] = a4.x; As[kq+1][m] = a4.y;
            As[kq+2][m] = a4.z; As[kq+3][m] = a4.w;
        }
        if (TB) {
            int n  = tid >> 2;
            int kq = (tid & 3) * 4;
            float4 b4 = *reinterpret_cast<const float4*>(
                &Bb[(long long)(bn0 + n) * K + k0 + kq]);
            Bs[kq+0][n] = b4.x; Bs[kq+1][n] = b4.y;
            Bs[kq+2][n] = b4.z; Bs[kq+3][n] = b4.w;
        } else {
            int k  = tid >> 4;            // 0..15
            int nq = (tid & 15) * 4;      // 0..60
            float4 b4 = *reinterpret_cast<const float4*>(
                &Bb[(long long)(k0 + k) * N + bn0 + nq]);
            Bs[k][nq+0] = b4.x; Bs[k][nq+1] = b4.y;
            Bs[k][nq+2] = b4.z; Bs[k][nq+3] = b4.w;
        }
        __syncthreads();

        #pragma unroll
        for (int k = 0; k < 16; k++) {
            float a[4], b[4];
            #pragma unroll
            for (int i = 0; i < 4; i++) a[i] = As[k][ty*4 + i];
            #pragma unroll
            for (int j = 0; j < 4; j++) b[j] = Bs[k][tx*4 + j];
            #pragma unroll
            for (int i = 0; i < 4; i++)
                #pragma unroll
                for (int j = 0; j < 4; j++)
                    acc[i][j] = fmaf(a[i], b[j], acc[i][j]);
        }
        __syncthreads();
    }

    #pragma unroll
    for (int i = 0; i < 4; i++) {
        int m = bm0 + ty*4 + i;
        #pragma unroll
        for (int j = 0; j < 4; j++) {
            int n = bn0 + tx*4 + j;
            float v = acc[i][j] * alpha;
            if (bias) v += bias[n];
            if (relu) v = fmaxf(v, 0.0f);
            Cb[(long long)m * N + n] = v;
        }
    }
}

// ---------------- block reductions -------------------------------------------
__device__ __forceinline__ float warpMax(float v) {
    #pragma unroll
    for (int o = 16; o > 0; o >>= 1) v = fmaxf(v, __shfl_xor_sync(0xffffffffu, v, o));
    return v;
}
__device__ __forceinline__ float warpSum(float v) {
    #pragma unroll
    for (int o = 16; o > 0; o >>= 1) v += __shfl_xor_sync(0xffffffffu, v, o);
    return v;
}
__device__ __forceinline__ float blockMax(float v) {
    __shared__ float sh[8];
    v = warpMax(v);
    __syncthreads();
    if ((threadIdx.x & 31) == 0) sh[threadIdx.x >> 5] = v;
    __syncthreads();
    float r = -1e30f;
    int nw = blockDim.x >> 5;
    #pragma unroll
    for (int i = 0; i < 8; i++) if (i < nw) r = fmaxf(r, sh[i]);
    return r;
}
__device__ __forceinline__ float blockSum(float v) {
    __shared__ float sh[8];
    v = warpSum(v);
    __syncthreads();
    if ((threadIdx.x & 31) == 0) sh[threadIdx.x >> 5] = v;
    __syncthreads();
    float r = 0.0f;
    int nw = blockDim.x >> 5;
    #pragma unroll
    for (int i = 0; i < 8; i++) if (i < nw) r += sh[i];
    return r;
}

// ---------------- fused dual softmax + blend (in place on mixed) --------------
// blended = TT * softmax(mixed) + (1-TT) * softmax(att), row length T1=2048.
// One block per row, 256 threads, 8 elements per thread.
__global__ void __launch_bounds__(256)
softmax_blend_kernel(float* __restrict__ mixed, const float* __restrict__ att)
{
    const long long base = (long long)blockIdx.x * T1_;
    const int tid = threadIdx.x;

    float mv[8], av[8];
    float m1 = -1e30f, m2 = -1e30f;
    #pragma unroll
    for (int i = 0; i < 8; i++) {
        int c = tid + i * 256;
        mv[i] = mixed[base + c];
        av[i] = att[base + c];
        m1 = fmaxf(m1, mv[i]);
        m2 = fmaxf(m2, av[i]);
    }
    m1 = blockMax(m1);
    m2 = blockMax(m2);

    float s1 = 0.f, s2 = 0.f;
    #pragma unroll
    for (int i = 0; i < 8; i++) {
        mv[i] = __expf(mv[i] - m1);
        av[i] = __expf(av[i] - m2);
        s1 += mv[i];
        s2 += av[i];
    }
    s1 = blockSum(s1);
    s2 = blockSum(s2);
    const float r1 = TTMIX / s1;
    const float r2 = (1.0f - TTMIX) / s2;

    #pragma unroll
    for (int i = 0; i < 8; i++) {
        int c = tid + i * 256;
        mixed[base + c] = mv[i] * r1 + av[i] * r2;
    }
}

// ---------------- fused residual add + LayerNorm (in place on x) -------------
// x = LN(x + z) * g + b,  row length D=384. One block/row, 128 threads, 3/thread.
__global__ void __launch_bounds__(128)
add_ln_kernel(float* __restrict__ x, const float* __restrict__ z,
              const float* __restrict__ g, const float* __restrict__ b)
{
    const long long base = (long long)blockIdx.x * DD;
    const int tid = threadIdx.x;

    float v[3];
    #pragma unroll
    for (int i = 0; i < 3; i++) v[i] = x[base + tid + i*128] + z[base + tid + i*128];

    float s = v[0] + v[1] + v[2];
    s = blockSum(s);
    const float mean = s * (1.0f / DD);

    float q = 0.f;
    #pragma unroll
    for (int i = 0; i < 3; i++) { float d = v[i] - mean; q += d * d; }
    q = blockSum(q);
    const float rstd = rsqrtf(q * (1.0f / DD) + LN_EPS);

    #pragma unroll
    for (int i = 0; i < 3; i++) {
        int c = tid + i * 128;
        x[base + c] = (v[i] - mean) * rstd * g[c] + b[c];
    }
}

// ---------------- host-side helpers ------------------------------------------
static inline void gemm(const float* A, const float* Bm, const float* bias, float* C,
                        int M, int N, int K, float alpha, bool transb, bool relu,
                        int batch, long long sA, long long sB, long long sC)
{
    dim3 grid(N / 64, M / 64, batch), block(256);
    if (transb)
        sgemm_kernel<1><<<grid, block>>>(A, Bm, bias, C, M, N, K, alpha, relu ? 1 : 0, sA, sB, sC);
    else
        sgemm_kernel<0><<<grid, block>>>(A, Bm, bias, C, M, N, K, alpha, relu ? 1 : 0, sA, sB, sC);
}

extern "C" void kernel_launch(void* const* d_in, const int* in_sizes, int n_in,
                              void* d_out, int out_size)
{
    (void)in_sizes; (void)n_in; (void)out_size;
    const float* tgt     = (const float*)d_in[0];
    const float* memory  = (const float*)d_in[1];
    const float* score_c = (const float*)d_in[2];
    const float* out_c   = (const float*)d_in[3];
    const float* Wq  = (const float*)d_in[4];
    const float* bq  = (const float*)d_in[5];
    const float* Wk  = (const float*)d_in[6];
    const float* bk  = (const float*)d_in[7];
    const float* Wv  = (const float*)d_in[8];
    const float* bv  = (const float*)d_in[9];
    const float* Wkn = (const float*)d_in[10];
    const float* bkn = (const float*)d_in[11];
    const float* Wun = (const float*)d_in[12];
    const float* bun = (const float*)d_in[13];
    const float* W1  = (const float*)d_in[14];
    const float* b1  = (const float*)d_in[15];
    const float* W2  = (const float*)d_in[16];
    const float* b2  = (const float*)d_in[17];
    const float* g1  = (const float*)d_in[18];
    const float* be1 = (const float*)d_in[19];
    const float* g2  = (const float*)d_in[20];
    const float* be2 = (const float*)d_in[21];

    float *gx, *gq, *gk, *gv, *gatt, *gunk, *gkno, *gs1, *gmix, *gz, *gh;
    cudaGetSymbolAddress((void**)&gx,  g_x);
    cudaGetSymbolAddress((void**)&gq,  g_q);
    cudaGetSymbolAddress((void**)&gk,  g_k);
    cudaGetSymbolAddress((void**)&gv,  g_v);
    cudaGetSymbolAddress((void**)&gatt, g_att);
    cudaGetSymbolAddress((void**)&gunk, g_unk);
    cudaGetSymbolAddress((void**)&gkno, g_kno);
    cudaGetSymbolAddress((void**)&gs1, g_s1);
    cudaGetSymbolAddress((void**)&gmix, g_mix);
    cudaGetSymbolAddress((void**)&gz,  g_z);
    cudaGetSymbolAddress((void**)&gh,  g_h);

    const float scale = 1.0f / sqrtf((float)DD);
    const long long BT  = (long long)BN * TT_;   // 4096 rows (x-space)
    const long long BS  = (long long)BN * T1_;   // 8192 rows (memory-space)

    // x <- tgt
    cudaMemcpyAsync(gx, tgt, BT * DD * sizeof(float), cudaMemcpyDeviceToDevice);

    for (int l = 0; l < LY; l++) {
        const float* Wq_l  = Wq  + (long long)l * DD * DD;
        const float* Wk_l  = Wk  + (long long)l * DD * DKK;
        const float* Wv_l  = Wv  + (long long)l * DD * DKK;
        const float* Wkn_l = Wkn + (long long)l * DD * DD;
        const float* Wun_l = Wun + (long long)l * DD * DD;
        const float* W1_l  = W1  + (long long)l * FFF * DD;
        const float* W2_l  = W2  + (long long)l * DD * FFF;
        const float* oc_l  = out_c + (long long)l * BN * TCC * DD;
        const float* sc_l  = score_c + (long long)l * BN * TCC * T1_;

        // q = x @ Wq^T + bq            [4096, 384]
        gemm(gx, Wq_l, bq + (long long)l*DD, gq, (int)BT, DD, DD, 1.0f, true, false, 1, 0, 0, 0);
        // k = memory @ Wk^T + bk       [8192, 384]
        gemm(memory, Wk_l, bk + (long long)l*DD, gk, (int)BS, DD, DKK, 1.0f, true, false, 1, 0, 0, 0);
        // v = memory @ Wv^T + bv
        gemm(memory, Wv_l, bv + (long long)l*DD, gv, (int)BS, DD, DKK, 1.0f, true, false, 1, 0, 0, 0);
        // att = scale * q @ k^T        batched [B][1024, 2048]
        gemm(gq, gk, nullptr, gatt, TT_, T1_, DD, scale, true, false, BN,
             (long long)TT_*DD, (long long)T1_*DD, (long long)TT_*T1_);
        // unk = x @ Wun^T + bun
        gemm(gx, Wun_l, bun + (long long)l*DD, gunk, (int)BT, DD, DD, 1.0f, true, false, 1, 0, 0, 0);
        // kno = out_c[l] @ Wkn^T + bkn [4096, 384]
        gemm(oc_l, Wkn_l, bkn + (long long)l*DD, gkno, BN*TCC, DD, DD, 1.0f, true, false, 1, 0, 0, 0);
        // score1 = scale * unk @ kno^T  batched [B][1024, 1024]
        gemm(gunk, gkno, nullptr, gs1, TT_, TCC, DD, scale, true, false, BN,
             (long long)TT_*DD, (long long)TCC*DD, (long long)TT_*TCC);
        // mixed = score1 @ score_c[l]   batched [B][1024, 2048], K=1024 (dominant)
        gemm(gs1, sc_l, nullptr, gmix, TT_, T1_, TCC, 1.0f, false, false, BN,
             (long long)TT_*TCC, (long long)TCC*T1_, (long long)TT_*T1_);
        // blended (in place on gmix)
        softmax_blend_kernel<<<(int)BT, 256>>>(gmix, gatt);
        // z = blended @ v               batched [B][1024, 384], K=2048
        gemm(gmix, gv, nullptr, gz, TT_, DD, T1_, 1.0f, false, false, BN,
             (long long)TT_*T1_, (long long)T1_*DD, (long long)TT_*DD);
        // x = LN(x + z)
        add_ln_kernel<<<(int)BT, 128>>>(gx, gz, g1 + (long long)l*DD, be1 + (long long)l*DD);
        // h = relu(x @ W1^T + b1)       [4096, 1536]
        gemm(gx, W1_l, b1 + (long long)l*FFF, gh, (int)BT, FFF, DD, 1.0f, true, true, 1, 0, 0, 0);
        // y2 = h @ W2^T + b2 (into gz)
        gemm(gh, W2_l, b2 + (long long)l*DD, gz, (int)BT, DD, FFF, 1.0f, true, false, 1, 0, 0, 0);
        // x = LN(x + y2)
        add_ln_kernel<<<(int)BT, 128>>>(gx, gz, g2 + (long long)l*DD, be2 + (long long)l*DD);
    }

    cudaMemcpyAsync(d_out, gx, BT * DD * sizeof(float), cudaMemcpyDeviceToDevice);
}

// round 3
// speedup vs baseline: 3.0257x; 3.0257x over previous
#include <cuda_runtime.h>
#include <cuda_bf16.h>
#include <math.h>
#include <stdint.h>

typedef __nv_bfloat16 bf16;

// ---------------- problem dims ----------------
#define LY 4
#define BN 4
#define T_ 1024
#define TC 1024
#define T1 2048
#define D_ 384
#define DK 256
#define FF 1536
#define TTMIX 0.1f
#define LN_EPS 1e-5f

#define NX   (BN*T_*D_)
#define NKV  (BN*T1*D_)
#define NAT  (BN*T_*T1)
#define NS1  (BN*T_*TC)
#define NH_  (BN*T_*FF)
#define NMEM (BN*T1*DK)
#define NOC  (LY*BN*TC*D_)
#define NSCT (BN*T1*TC)
#define NWQ  (LY*D_*D_)
#define NWK  (LY*D_*DK)
#define NW1  (LY*FF*D_)

// ---------------- scratch ----------------
__device__ __align__(128) float g_x[NX], g_att[NAT], g_mix[NAT], g_z[NX];
__device__ __align__(128) bf16 g_xh[NX], g_xl[NX], g_qh[NX], g_ql[NX];
__device__ __align__(128) bf16 g_kh[NKV], g_kl[NKV], g_vth[NKV], g_vtl[NKV];
__device__ __align__(128) bf16 g_unh[NX], g_unl[NX], g_knh[NX], g_knl[NX];
__device__ __align__(128) bf16 g_s1h[NS1], g_s1l[NS1], g_blh[NAT], g_bll[NAT];
__device__ __align__(128) bf16 g_hh[NH_], g_hl[NH_];
__device__ __align__(128) bf16 g_mh[NMEM], g_ml[NMEM], g_oh[NOC], g_ol[NOC];
__device__ __align__(128) bf16 g_sth[NSCT], g_stl[NSCT];
__device__ __align__(128) bf16 g_wqh[NWQ], g_wql[NWQ], g_wkh[NWK], g_wkl[NWK];
__device__ __align__(128) bf16 g_wvh[NWK], g_wvl[NWK], g_wnh[NWQ], g_wnl[NWQ];
__device__ __align__(128) bf16 g_wuh[NWQ], g_wul[NWQ];
__device__ __align__(128) bf16 g_w1h[NW1], g_w1l[NW1], g_w2h[NW1], g_w2l[NW1];

// ---------------- helpers ----------------
__device__ __forceinline__ uint32_t u32smem(const void* p) {
    uint32_t a;
    asm("{ .reg .u64 t; cvta.to.shared.u64 t, %1; cvt.u32.u64 %0, t; }" : "=r"(a) : "l"(p));
    return a;
}
__device__ __forceinline__ void cpa16(uint32_t s, const void* g) {
    asm volatile("cp.async.cg.shared.global [%0], [%1], 16;" :: "r"(s), "l"(g));
}
#define CP_COMMIT() asm volatile("cp.async.commit_group;" ::: "memory")
#define CP_WAIT(n)  asm volatile("cp.async.wait_group %0;" :: "n"(n) : "memory")

__device__ __forceinline__ void ldsm_x4(uint32_t& r0, uint32_t& r1, uint32_t& r2,
                                        uint32_t& r3, uint32_t a) {
    asm volatile("ldmatrix.sync.aligned.m8n8.x4.shared.b16 {%0,%1,%2,%3}, [%4];"
                 : "=r"(r0), "=r"(r1), "=r"(r2), "=r"(r3) : "r"(a));
}
__device__ __forceinline__ void mma16816(float* d, const uint32_t* a, const uint32_t* b) {
    asm volatile(
        "mma.sync.aligned.m16n8k16.row.col.f32.bf16.bf16.f32 "
        "{%0,%1,%2,%3},{%4,%5,%6,%7},{%8,%9},{%0,%1,%2,%3};"
        : "+f"(d[0]), "+f"(d[1]), "+f"(d[2]), "+f"(d[3])
        : "r"(a[0]), "r"(a[1]), "r"(a[2]), "r"(a[3]), "r"(b[0]), "r"(b[1]));
}
__device__ __forceinline__ bf16 bhi(float x) { return __float2bfloat16(x); }
__device__ __forceinline__ bf16 blo(float x, bf16 h) { return __float2bfloat16(x - __bfloat162float(h)); }

// ---------------- split-bf16 tensor GEMM: C = alpha*A@B^T (+bias)(+relu) -----
// A:[M,K] hi/lo, B:[N,K] hi/lo (K-major). CTA 128x128, BK=32, 256 thr, cp.async
// 2-stage. flags: 1=relu, 2=bias indexed by row (else by col).
__global__ void __launch_bounds__(256)
mma_gemm(const bf16* __restrict__ Ah, const bf16* __restrict__ Al,
         const bf16* __restrict__ Bh, const bf16* __restrict__ Bl,
         const float* __restrict__ bias, float alpha, int flags,
         float* __restrict__ Cf, bf16* __restrict__ Ch, bf16* __restrict__ Cl,
         int M, int N, int K, long long sA, long long sB, long long sC)
{
    extern __shared__ char sm[];
    const int tid = threadIdx.x, lane = tid & 31, wid = tid >> 5;
    const int wm = wid & 3, wn = wid >> 2;          // warp tile 32(m) x 64(n)
    const long long bz = blockIdx.z;
    const int bm0 = blockIdx.y << 7, bn0 = blockIdx.x << 7;

    const char* gsrc[4] = {
        (const char*)(Ah + bz * sA + (long long)bm0 * K),
        (const char*)(Al + bz * sA + (long long)bm0 * K),
        (const char*)(Bh + bz * sB + (long long)bn0 * K),
        (const char*)(Bl + bz * sB + (long long)bn0 * K) };
    const uint32_t sbase = u32smem(sm);
    const long long rowbytes = (long long)K * 2;

    float acc[2][8][4];
    #pragma unroll
    for (int i = 0; i < 2; i++)
        #pragma unroll
        for (int j = 0; j < 8; j++)
            #pragma unroll
            for (int q = 0; q < 4; q++) acc[i][j][q] = 0.f;

    const int nc = K >> 5;

    auto load_stage = [&](int buf, int k0) {
        uint32_t sb = sbase + buf * 32768;
        #pragma unroll
        for (int t = 0; t < 4; t++) {
            uint32_t ab = sb + t * 8192;
            const char* g = gsrc[t];
            #pragma unroll
            for (int i = 0; i < 2; i++) {
                int idx = i * 256 + tid;
                int r = idx >> 2, c = idx & 3;
                uint32_t so = ab + r * 64 + ((c ^ ((r >> 1) & 3)) << 4);
                cpa16(so, g + (long long)r * rowbytes + (long long)k0 * 2 + c * 16);
            }
        }
    };

    auto compute = [&](int buf) {
        uint32_t sb = sbase + buf * 32768;
        #pragma unroll
        for (int s = 0; s < 2; s++) {
            uint32_t a_h[2][4], a_l[2][4];
            #pragma unroll
            for (int mi = 0; mi < 2; mi++) {
                int row = wm * 32 + mi * 16 + (lane & 15);
                int kc  = 2 * s + (lane >> 4);
                uint32_t off = row * 64 + ((kc ^ ((row >> 1) & 3)) << 4);
                ldsm_x4(a_h[mi][0], a_h[mi][1], a_h[mi][2], a_h[mi][3], sb + off);
                ldsm_x4(a_l[mi][0], a_l[mi][1], a_l[mi][2], a_l[mi][3], sb + 8192 + off);
            }
            uint32_t b_h[8][2], b_l[8][2];
            #pragma unroll
            for (int nj = 0; nj < 4; nj++) {
                int row = wn * 64 + nj * 16 + (lane & 15);
                int kc  = 2 * s + (lane >> 4);
                uint32_t off = row * 64 + ((kc ^ ((row >> 1) & 3)) << 4);
                uint32_t r0, r1, r2, r3;
                ldsm_x4(r0, r1, r2, r3, sb + 16384 + off);
                b_h[2*nj][0] = r0; b_h[2*nj][1] = r2;
                b_h[2*nj+1][0] = r1; b_h[2*nj+1][1] = r3;
                ldsm_x4(r0, r1, r2, r3, sb + 24576 + off);
                b_l[2*nj][0] = r0; b_l[2*nj][1] = r2;
                b_l[2*nj+1][0] = r1; b_l[2*nj+1][1] = r3;
            }
            #pragma unroll
            for (int mi = 0; mi < 2; mi++)
                #pragma unroll
                for (int nb = 0; nb < 8; nb++) {
                    mma16816(acc[mi][nb], a_h[mi], b_h[nb]);
                    mma16816(acc[mi][nb], a_h[mi], b_l[nb]);
                    mma16816(acc[mi][nb], a_l[mi], b_h[nb]);
                }
        }
    };

    load_stage(0, 0);
    CP_COMMIT();
    for (int c = 0; c < nc; c++) {
        if (c + 1 < nc) {
            load_stage((c + 1) & 1, (c + 1) * 32);
            CP_COMMIT();
            CP_WAIT(1);
        } else {
            CP_WAIT(0);
        }
        __syncthreads();
        compute(c & 1);
        __syncthreads();
    }

    // ---- epilogue ----
    const int rl = lane >> 2, cl = (lane & 3) * 2;
    #pragma unroll
    for (int mi = 0; mi < 2; mi++) {
        #pragma unroll
        for (int hf = 0; hf < 2; hf++) {
            const long long grow = bm0 + wm * 32 + mi * 16 + rl + hf * 8;
            float brow = 0.f;
            if (bias && (flags & 2)) brow = bias[grow];
            const long long base = bz * sC + grow * (long long)N + bn0 + wn * 64;
            #pragma unroll
            for (int nb = 0; nb < 8; nb++) {
                const int coff = nb * 8 + cl;
                float v0 = acc[mi][nb][hf*2+0] * alpha;
                float v1 = acc[mi][nb][hf*2+1] * alpha;
                if (bias) {
                    if (flags & 2) { v0 += brow; v1 += brow; }
                    else {
                        const long long gcol = bn0 + wn * 64 + coff;
                        v0 += bias[gcol]; v1 += bias[gcol + 1];
                    }
                }
                if (flags & 1) { v0 = fmaxf(v0, 0.f); v1 = fmaxf(v1, 0.f); }
                if (Cf) *reinterpret_cast<float2*>(Cf + base + coff) = make_float2(v0, v1);
                if (Ch) {
                    bf16 h0 = bhi(v0), h1 = bhi(v1);
                    __nv_bfloat162 hh = __halves2bfloat162(h0, h1);
                    __nv_bfloat162 ll = __halves2bfloat162(blo(v0, h0), blo(v1, h1));
                    *reinterpret_cast<uint32_t*>(Ch + base + coff) = *reinterpret_cast<uint32_t*>(&hh);
                    *reinterpret_cast<uint32_t*>(Cl + base + coff) = *reinterpret_cast<uint32_t*>(&ll);
                }
            }
        }
    }
}

// ---------------- fp32 -> (hi,lo) bf16 split ----------------
__global__ void cvt_split(const float* __restrict__ in, bf16* __restrict__ hi,
                          bf16* __restrict__ lo, long long n4)
{
    long long i = blockIdx.x * (long long)blockDim.x + threadIdx.x;
    if (i >= n4) return;
    float4 v = reinterpret_cast<const float4*>(in)[i];
    bf16 h0 = bhi(v.x), h1 = bhi(v.y), h2 = bhi(v.z), h3 = bhi(v.w);
    __nv_bfloat162 a = __halves2bfloat162(h0, h1), b = __halves2bfloat162(h2, h3);
    __nv_bfloat162 c = __halves2bfloat162(blo(v.x, h0), blo(v.y, h1));
    __nv_bfloat162 d = __halves2bfloat162(blo(v.z, h2), blo(v.w, h3));
    reinterpret_cast<uint2*>(hi)[i] = make_uint2(*(uint32_t*)&a, *(uint32_t*)&b);
    reinterpret_cast<uint2*>(lo)[i] = make_uint2(*(uint32_t*)&c, *(uint32_t*)&d);
}

// ---------------- score_c transpose + split ----------------
__global__ void transpose_split(const float* __restrict__ in,
                                bf16* __restrict__ oh, bf16* __restrict__ ol)
{
    __shared__ float tile[32][33];
    const int b = blockIdx.z;
    const int x0 = blockIdx.x << 5;   // T1
    const int y0 = blockIdx.y << 5;   // TC
    const float* ib = in + (long long)b * TC * T1;
    const int tx = threadIdx.x, ty = threadIdx.y;
    #pragma unroll
    for (int i = 0; i < 4; i++)
        tile[ty + 8*i][tx] = ib[(long long)(y0 + ty + 8*i) * T1 + x0 + tx];
    __syncthreads();
    bf16* ohb = oh + (long long)b * T1 * TC;
    bf16* olb = ol + (long long)b * T1 * TC;
    #pragma unroll
    for (int i = 0; i < 4; i++) {
        float v = tile[tx][ty + 8*i];
        bf16 h = bhi(v);
        long long o = (long long)(x0 + ty + 8*i) * TC + y0 + tx;
        ohb[o] = h;
        olb[o] = blo(v, h);
    }
}

// ---------------- reductions ----------------
__device__ __forceinline__ float warpMax(float v) {
    #pragma unroll
    for (int o = 16; o > 0; o >>= 1) v = fmaxf(v, __shfl_xor_sync(0xffffffffu, v, o));
    return v;
}
__device__ __forceinline__ float warpSum(float v) {
    #pragma unroll
    for (int o = 16; o > 0; o >>= 1) v += __shfl_xor_sync(0xffffffffu, v, o);
    return v;
}
__device__ __forceinline__ float blockMax(float v) {
    __shared__ float sh[8];
    v = warpMax(v);
    __syncthreads();
    if ((threadIdx.x & 31) == 0) sh[threadIdx.x >> 5] = v;
    __syncthreads();
    float r = -1e30f;
    int nw = blockDim.x >> 5;
    #pragma unroll
    for (int i = 0; i < 8; i++) if (i < nw) r = fmaxf(r, sh[i]);
    return r;
}
__device__ __forceinline__ float blockSum(float v) {
    __shared__ float sh[8];
    v = warpSum(v);
    __syncthreads();
    if ((threadIdx.x & 31) == 0) sh[threadIdx.x >> 5] = v;
    __syncthreads();
    float r = 0.0f;
    int nw = blockDim.x >> 5;
    #pragma unroll
    for (int i = 0; i < 8; i++) if (i < nw) r += sh[i];
    return r;
}

// ---------------- dual softmax + blend -> hi/lo ----------------
__global__ void __launch_bounds__(256)
softmax_blend(const float* __restrict__ mixed, const float* __restrict__ att,
              bf16* __restrict__ oh, bf16* __restrict__ ol)
{
    const long long base = (long long)blockIdx.x * T1;
    const int tid = threadIdx.x;
    float mv[8], av[8];
    float m1 = -1e30f, m2 = -1e30f;
    #pragma unroll
    for (int i = 0; i < 8; i++) {
        int c = tid + i * 256;
        mv[i] = mixed[base + c];
        av[i] = att[base + c];
        m1 = fmaxf(m1, mv[i]);
        m2 = fmaxf(m2, av[i]);
    }
    m1 = blockMax(m1);
    m2 = blockMax(m2);
    float s1 = 0.f, s2 = 0.f;
    #pragma unroll
    for (int i = 0; i < 8; i++) {
        mv[i] = __expf(mv[i] - m1);
        av[i] = __expf(av[i] - m2);
        s1 += mv[i]; s2 += av[i];
    }
    s1 = blockSum(s1);
    s2 = blockSum(s2);
    const float r1 = TTMIX / s1, r2 = (1.0f - TTMIX) / s2;
    #pragma unroll
    for (int i = 0; i < 8; i++) {
        int c = tid + i * 256;
        float v = mv[i] * r1 + av[i] * r2;
        bf16 h = bhi(v);
        oh[base + c] = h;
        ol[base + c] = blo(v, h);
    }
}

// ---------------- residual add + LayerNorm -> fp32 + hi/lo ----------------
__global__ void __launch_bounds__(128)
add_ln(float* __restrict__ x, const float* __restrict__ z,
       const float* __restrict__ g, const float* __restrict__ b,
       bf16* __restrict__ xh, bf16* __restrict__ xl)
{
    const long long base = (long long)blockIdx.x * D_;
    const int tid = threadIdx.x;
    float v[3];
    #pragma unroll
    for (int i = 0; i < 3; i++) v[i] = x[base + tid + i*128] + z[base + tid + i*128];
    float s = v[0] + v[1] + v[2];
    s = blockSum(s);
    const float mean = s * (1.0f / D_);
    float q = 0.f;
    #pragma unroll
    for (int i = 0; i < 3; i++) { float d = v[i] - mean; q += d * d; }
    q = blockSum(q);
    const float rstd = rsqrtf(q * (1.0f / D_) + LN_EPS);
    #pragma unroll
    for (int i = 0; i < 3; i++) {
        int c = tid + i * 128;
        float o = (v[i] - mean) * rstd * g[c] + b[c];
        x[base + c] = o;
        bf16 h = bhi(o);
        xh[base + c] = h;
        xl[base + c] = blo(o, h);
    }
}

// ---------------- host ----------------
#define SMEM_DYN 65536
#define SYM(p, s) do { void* _t; cudaGetSymbolAddress(&_t, s); p = (decltype(p))_t; } while (0)

static void split(const float* in, bf16* hi, bf16* lo, long long n) {
    long long n4 = n / 4;
    cvt_split<<<(unsigned)((n4 + 255) / 256), 256>>>(in, hi, lo, n4);
}
static void gemm(const bf16* Ah, const bf16* Al, const bf16* Bh, const bf16* Bl,
                 const float* bias, float alpha, int flags,
                 float* Cf, bf16* Ch, bf16* Cl,
                 int M, int N, int K, int batch,
                 long long sA, long long sB, long long sC) {
    dim3 g(N / 128, M / 128, batch);
    mma_gemm<<<g, 256, SMEM_DYN>>>(Ah, Al, Bh, Bl, bias, alpha, flags,
                                   Cf, Ch, Cl, M, N, K, sA, sB, sC);
}

extern "C" void kernel_launch(void* const* d_in, const int* in_sizes, int n_in,
                              void* d_out, int out_size)
{
    (void)in_sizes; (void)n_in; (void)out_size;
    const float* tgt     = (const float*)d_in[0];
    const float* memory  = (const float*)d_in[1];
    const float* score_c = (const float*)d_in[2];
    const float* out_c   = (const float*)d_in[3];
    const float* Wq  = (const float*)d_in[4];
    const float* bq  = (const float*)d_in[5];
    const float* Wk  = (const float*)d_in[6];
    const float* bk  = (const float*)d_in[7];
    const float* Wv  = (const float*)d_in[8];
    const float* bv  = (const float*)d_in[9];
    const float* Wkn = (const float*)d_in[10];
    const float* bkn = (const float*)d_in[11];
    const float* Wun = (const float*)d_in[12];
    const float* bun = (const float*)d_in[13];
    const float* W1  = (const float*)d_in[14];
    const float* b1  = (const float*)d_in[15];
    const float* W2  = (const float*)d_in[16];
    const float* b2  = (const float*)d_in[17];
    const float* g1  = (const float*)d_in[18];
    const float* be1 = (const float*)d_in[19];
    const float* g2  = (const float*)d_in[20];
    const float* be2 = (const float*)d_in[21];

    float *x, *att, *mix, *z;
    SYM(x, g_x); SYM(att, g_att); SYM(mix, g_mix); SYM(z, g_z);
    bf16 *xh,*xl,*qh,*ql,*kh,*kl,*vth,*vtl,*unh,*unl,*knh,*knl,*s1h,*s1l,*blh,*bll,*hh,*hl;
    bf16 *mh,*ml,*oh,*ol,*sth,*stl;
    bf16 *wqh,*wql,*wkh,*wkl,*wvh,*wvl,*wnh,*wnl,*wuh,*wul,*w1h,*w1l,*w2h,*w2l;
    SYM(xh,g_xh); SYM(xl,g_xl); SYM(qh,g_qh); SYM(ql,g_ql);
    SYM(kh,g_kh); SYM(kl,g_kl); SYM(vth,g_vth); SYM(vtl,g_vtl);
    SYM(unh,g_unh); SYM(unl,g_unl); SYM(knh,g_knh); SYM(knl,g_knl);
    SYM(s1h,g_s1h); SYM(s1l,g_s1l); SYM(blh,g_blh); SYM(bll,g_bll);
    SYM(hh,g_hh); SYM(hl,g_hl); SYM(mh,g_mh); SYM(ml,g_ml);
    SYM(oh,g_oh); SYM(ol,g_ol); SYM(sth,g_sth); SYM(stl,g_stl);
    SYM(wqh,g_wqh); SYM(wql,g_wql); SYM(wkh,g_wkh); SYM(wkl,g_wkl);
    SYM(wvh,g_wvh); SYM(wvl,g_wvl); SYM(wnh,g_wnh); SYM(wnl,g_wnl);
    SYM(wuh,g_wuh); SYM(wul,g_wul);
    SYM(w1h,g_w1h); SYM(w1l,g_w1l); SYM(w2h,g_w2h); SYM(w2l,g_w2l);

    cudaFuncSetAttribute(mma_gemm, cudaFuncAttributeMaxDynamicSharedMemorySize, SMEM_DYN);

    const float scale = 1.0f / sqrtf((float)D_);

    // one-time conversions
    cudaMemcpyAsync(x, tgt, (size_t)NX * 4, cudaMemcpyDeviceToDevice);
    split(tgt, xh, xl, NX);
    split(memory, mh, ml, NMEM);
    split(out_c, oh, ol, NOC);
    split(Wq, wqh, wql, NWQ);
    split(Wk, wkh, wkl, NWK);
    split(Wv, wvh, wvl, NWK);
    split(Wkn, wnh, wnl, NWQ);
    split(Wun, wuh, wul, NWQ);
    split(W1, w1h, w1l, NW1);
    split(W2, w2h, w2l, NW1);

    for (int l = 0; l < LY; l++) {
        const long long oq = (long long)l * D_ * D_;
        const long long ok = (long long)l * D_ * DK;
        const long long o1 = (long long)l * FF * D_;
        // q = x @ Wq^T + bq
        gemm(xh, xl, wqh + oq, wql + oq, bq + l*D_, 1.f, 0, nullptr, qh, ql,
             BN*T_, D_, D_, 1, 0, 0, 0);
        // k = memory @ Wk^T + bk
        gemm(mh, ml, wkh + ok, wkl + ok, bk + l*D_, 1.f, 0, nullptr, kh, kl,
             BN*T1, D_, DK, 1, 0, 0, 0);
        // vT_b = Wv @ memory_b^T + bv (row bias)
        gemm(wvh + ok, wvl + ok, mh, ml, bv + l*D_, 1.f, 2, nullptr, vth, vtl,
             D_, T1, DK, BN, 0, (long long)T1*DK, (long long)D_*T1);
        // att = scale * q_b @ k_b^T
        gemm(qh, ql, kh, kl, nullptr, scale, 0, att, nullptr, nullptr,
             T_, T1, D_, BN, (long long)T_*D_, (long long)T1*D_, (long long)T_*T1);
        // unk = x @ Wun^T + bun
        gemm(xh, xl, wuh + oq, wul + oq, bun + l*D_, 1.f, 0, nullptr, unh, unl,
             BN*T_, D_, D_, 1, 0, 0, 0);
        // kno = out_c[l] @ Wkn^T + bkn
        gemm(oh + (long long)l*BN*TC*D_, ol + (long long)l*BN*TC*D_,
             wnh + oq, wnl + oq, bkn + l*D_, 1.f, 0, nullptr, knh, knl,
             BN*TC, D_, D_, 1, 0, 0, 0);
        // score1 = scale * unk_b @ kno_b^T
        gemm(unh, unl, knh, knl, nullptr, scale, 0, nullptr, s1h, s1l,
             T_, TC, D_, BN, (long long)T_*D_, (long long)TC*D_, (long long)T_*TC);
        // score_c[l]^T (+split)
        {
            dim3 g(T1/32, TC/32, BN), b(32, 8);
            transpose_split<<<g, b>>>(score_c + (long long)l*BN*TC*T1, sth, stl);
        }
        // mixed = score1_b @ score_cT_b^T
        gemm(s1h, s1l, sth, stl, nullptr, 1.f, 0, mix, nullptr, nullptr,
             T_, T1, TC, BN, (long long)T_*TC, (long long)T1*TC, (long long)T_*T1);
        // blended = TT*softmax(mixed) + (1-TT)*softmax(att)
        softmax_blend<<<BN*T_, 256>>>(mix, att, blh, bll);
        // z = blended_b @ vT_b^T
        gemm(blh, bll, vth, vtl, nullptr, 1.f, 0, z, nullptr, nullptr,
             T_, D_, T1, BN, (long long)T_*T1, (long long)D_*T1, (long long)T_*D_);
        // x = LN(x + z)
        add_ln<<<BN*T_, 128>>>(x, z, g1 + l*D_, be1 + l*D_, xh, xl);
        // h = relu(x @ W1^T + b1)
        gemm(xh, xl, w1h + o1, w1l + o1, b1 + l*FF, 1.f, 1, nullptr, hh, hl,
             BN*T_, FF, D_, 1, 0, 0, 0);
        // y2 = h @ W2^T + b2  (into z)
        gemm(hh, hl, w2h + o1, w2l + o1, b2 + l*D_, 1.f, 0, z, nullptr, nullptr,
             BN*T_, D_, FF, 1, 0, 0, 0);
        // x = LN(x + y2)
        add_ln<<<BN*T_, 128>>>(x, z, g2 + l*D_, be2 + l*D_, xh, xl);
    }

    cudaMemcpyAsync(d_out, x, (size_t)NX * 4, cudaMemcpyDeviceToDevice);
}

// round 4
// speedup vs baseline: 3.2641x; 1.0788x over previous
#include <cuda_runtime.h>
#include <cuda_bf16.h>
#include <math.h>
#include <stdint.h>

typedef __nv_bfloat16 bf16;

// ---------------- problem dims ----------------
#define LY 4
#define BN 4
#define T_ 1024
#define TC 1024
#define T1 2048
#define D_ 384
#define DK 256
#define FF 1536
#define TTMIX 0.1f
#define LN_EPS 1e-5f

#define NX   (BN*T_*D_)
#define NKV  (BN*T1*D_)
#define NAT  (BN*T_*T1)
#define NS1  (BN*T_*TC)
#define NH_  (BN*T_*FF)
#define NMEM (BN*T1*DK)
#define NOC  (LY*BN*TC*D_)
#define NSCT (BN*T1*TC)
#define NWQ  (LY*D_*D_)
#define NWK  (LY*D_*DK)
#define NW1  (LY*FF*D_)

// ---------------- scratch ----------------
__device__ __align__(128) float g_x[NX], g_att[NAT], g_mix[NAT], g_z[NX];
__device__ __align__(128) bf16 g_xh[NX], g_xl[NX], g_qh[NX], g_ql[NX];
__device__ __align__(128) bf16 g_kh[NKV], g_kl[NKV], g_vth[NKV], g_vtl[NKV];
__device__ __align__(128) bf16 g_unh[NX], g_unl[NX], g_knh[NX], g_knl[NX];
__device__ __align__(128) bf16 g_s1h[NS1], g_s1l[NS1], g_blh[NAT], g_bll[NAT];
__device__ __align__(128) bf16 g_hh[NH_], g_hl[NH_];
__device__ __align__(128) bf16 g_mh[NMEM], g_ml[NMEM], g_oh[NOC], g_ol[NOC];
__device__ __align__(128) bf16 g_sth[NSCT], g_stl[NSCT];
__device__ __align__(128) bf16 g_wqh[NWQ], g_wql[NWQ], g_wkh[NWK], g_wkl[NWK];
__device__ __align__(128) bf16 g_wvh[NWK], g_wvl[NWK], g_wnh[NWQ], g_wnl[NWQ];
__device__ __align__(128) bf16 g_wuh[NWQ], g_wul[NWQ];
__device__ __align__(128) bf16 g_w1h[NW1], g_w1l[NW1], g_w2h[NW1], g_w2l[NW1];

// ---------------- helpers ----------------
__device__ __forceinline__ uint32_t u32smem(const void* p) {
    uint32_t a;
    asm("{ .reg .u64 t; cvta.to.shared.u64 t, %1; cvt.u32.u64 %0, t; }" : "=r"(a) : "l"(p));
    return a;
}
__device__ __forceinline__ void cpa16(uint32_t s, const void* g) {
    asm volatile("cp.async.cg.shared.global [%0], [%1], 16;" :: "r"(s), "l"(g));
}
#define CP_COMMIT() asm volatile("cp.async.commit_group;" ::: "memory")
#define CP_WAIT(n)  asm volatile("cp.async.wait_group %0;" :: "n"(n) : "memory")

__device__ __forceinline__ void ldsm_x4(uint32_t& r0, uint32_t& r1, uint32_t& r2,
                                        uint32_t& r3, uint32_t a) {
    asm volatile("ldmatrix.sync.aligned.m8n8.x4.shared.b16 {%0,%1,%2,%3}, [%4];"
                 : "=r"(r0), "=r"(r1), "=r"(r2), "=r"(r3) : "r"(a));
}
__device__ __forceinline__ void mma16816(float* d, const uint32_t* a, const uint32_t* b) {
    asm volatile(
        "mma.sync.aligned.m16n8k16.row.col.f32.bf16.bf16.f32 "
        "{%0,%1,%2,%3},{%4,%5,%6,%7},{%8,%9},{%0,%1,%2,%3};"
        : "+f"(d[0]), "+f"(d[1]), "+f"(d[2]), "+f"(d[3])
        : "r"(a[0]), "r"(a[1]), "r"(a[2]), "r"(a[3]), "r"(b[0]), "r"(b[1]));
}
__device__ __forceinline__ bf16 bhi(float x) { return __float2bfloat16(x); }
__device__ __forceinline__ bf16 blo(float x, bf16 h) { return __float2bfloat16(x - __bfloat162float(h)); }

// ---------------- split-bf16 tensor GEMM: C = alpha*A@B^T (+bias)(+relu) -----
// A:[M,K] hi/lo, B:[N,K] hi/lo (K-major). CTA 128x128, BK=32, 3-stage cp.async,
// 2 CTAs/SM. flags: 1=relu, 2=bias indexed by row (else by col).
#define STAGES 3
#define STAGE_BYTES 32768

__global__ void __launch_bounds__(256, 2)
mma_gemm(const bf16* __restrict__ Ah, const bf16* __restrict__ Al,
         const bf16* __restrict__ Bh, const bf16* __restrict__ Bl,
         const float* __restrict__ bias, float alpha, int flags,
         float* __restrict__ Cf, bf16* __restrict__ Ch, bf16* __restrict__ Cl,
         int M, int N, int K, long long sA, long long sB, long long sC)
{
    extern __shared__ char sm[];
    const int tid = threadIdx.x, lane = tid & 31, wid = tid >> 5;
    const int wm = wid & 3, wn = wid >> 2;          // warp tile 32(m) x 64(n)
    const long long bz = blockIdx.z;
    const int bm0 = blockIdx.y << 7, bn0 = blockIdx.x << 7;

    const char* gsrc[4] = {
        (const char*)(Ah + bz * sA + (long long)bm0 * K),
        (const char*)(Al + bz * sA + (long long)bm0 * K),
        (const char*)(Bh + bz * sB + (long long)bn0 * K),
        (const char*)(Bl + bz * sB + (long long)bn0 * K) };
    const uint32_t sbase = u32smem(sm);
    const long long rowbytes = (long long)K * 2;

    float acc[2][8][4];
    #pragma unroll
    for (int i = 0; i < 2; i++)
        #pragma unroll
        for (int j = 0; j < 8; j++)
            #pragma unroll
            for (int q = 0; q < 4; q++) acc[i][j][q] = 0.f;

    const int nc = K >> 5;

    auto load_stage = [&](int buf, int k0) {
        uint32_t sb = sbase + buf * STAGE_BYTES;
        #pragma unroll
        for (int t = 0; t < 4; t++) {
            uint32_t ab = sb + t * 8192;
            const char* g = gsrc[t];
            #pragma unroll
            for (int i = 0; i < 2; i++) {
                int idx = i * 256 + tid;
                int r = idx >> 2, c = idx & 3;
                uint32_t so = ab + r * 64 + ((c ^ ((r >> 1) & 3)) << 4);
                cpa16(so, g + (long long)r * rowbytes + (long long)k0 * 2 + c * 16);
            }
        }
    };

    auto compute = [&](int buf) {
        uint32_t sb = sbase + buf * STAGE_BYTES;
        #pragma unroll
        for (int s = 0; s < 2; s++) {
            uint32_t a_h[2][4], a_l[2][4];
            #pragma unroll
            for (int mi = 0; mi < 2; mi++) {
                int row = wm * 32 + mi * 16 + (lane & 15);
                int kc  = 2 * s + (lane >> 4);
                uint32_t off = row * 64 + ((kc ^ ((row >> 1) & 3)) << 4);
                ldsm_x4(a_h[mi][0], a_h[mi][1], a_h[mi][2], a_h[mi][3], sb + off);
                ldsm_x4(a_l[mi][0], a_l[mi][1], a_l[mi][2], a_l[mi][3], sb + 8192 + off);
            }
            #pragma unroll
            for (int nj = 0; nj < 4; nj++) {
                int row = wn * 64 + nj * 16 + (lane & 15);
                int kc  = 2 * s + (lane >> 4);
                uint32_t off = row * 64 + ((kc ^ ((row >> 1) & 3)) << 4);
                uint32_t h0, h1, h2, h3, l0, l1, l2, l3;
                ldsm_x4(h0, h1, h2, h3, sb + 16384 + off);
                ldsm_x4(l0, l1, l2, l3, sb + 24576 + off);
                uint32_t bh0[2] = {h0, h2}, bh1[2] = {h1, h3};
                uint32_t bl0[2] = {l0, l2}, bl1[2] = {l1, l3};
                #pragma unroll
                for (int mi = 0; mi < 2; mi++) {
                    mma16816(acc[mi][2*nj],   a_h[mi], bh0);
                    mma16816(acc[mi][2*nj],   a_h[mi], bl0);
                    mma16816(acc[mi][2*nj],   a_l[mi], bh0);
                    mma16816(acc[mi][2*nj+1], a_h[mi], bh1);
                    mma16816(acc[mi][2*nj+1], a_h[mi], bl1);
                    mma16816(acc[mi][2*nj+1], a_l[mi], bh1);
                }
            }
        }
    };

    #pragma unroll
    for (int s = 0; s < STAGES - 1; s++) {
        if (s < nc) load_stage(s, s * 32);
        CP_COMMIT();
    }
    int buf = 0, nxt = STAGES - 1;
    for (int c = 0; c < nc; c++) {
        CP_WAIT(STAGES - 2);
        __syncthreads();
        if (c + STAGES - 1 < nc) {
            load_stage(nxt, (c + STAGES - 1) * 32);
            CP_COMMIT();
        } else {
            CP_COMMIT();   // keep group count in sync for CP_WAIT
        }
        compute(buf);
        if (++buf == STAGES) buf = 0;
        if (++nxt == STAGES) nxt = 0;
    }

    // ---- epilogue ----
    const int rl = lane >> 2, cl = (lane & 3) * 2;
    #pragma unroll
    for (int mi = 0; mi < 2; mi++) {
        #pragma unroll
        for (int hf = 0; hf < 2; hf++) {
            const long long grow = bm0 + wm * 32 + mi * 16 + rl + hf * 8;
            float brow = 0.f;
            if (bias && (flags & 2)) brow = bias[grow];
            const long long base = bz * sC + grow * (long long)N + bn0 + wn * 64;
            #pragma unroll
            for (int nb = 0; nb < 8; nb++) {
                const int coff = nb * 8 + cl;
                float v0 = acc[mi][nb][hf*2+0] * alpha;
                float v1 = acc[mi][nb][hf*2+1] * alpha;
                if (bias) {
                    if (flags & 2) { v0 += brow; v1 += brow; }
                    else {
                        const long long gcol = bn0 + wn * 64 + coff;
                        v0 += bias[gcol]; v1 += bias[gcol + 1];
                    }
                }
                if (flags & 1) { v0 = fmaxf(v0, 0.f); v1 = fmaxf(v1, 0.f); }
                if (Cf) *reinterpret_cast<float2*>(Cf + base + coff) = make_float2(v0, v1);
                if (Ch) {
                    bf16 h0 = bhi(v0), h1 = bhi(v1);
                    __nv_bfloat162 hh = __halves2bfloat162(h0, h1);
                    __nv_bfloat162 ll = __halves2bfloat162(blo(v0, h0), blo(v1, h1));
                    *reinterpret_cast<uint32_t*>(Ch + base + coff) = *reinterpret_cast<uint32_t*>(&hh);
                    *reinterpret_cast<uint32_t*>(Cl + base + coff) = *reinterpret_cast<uint32_t*>(&ll);
                }
            }
        }
    }
}

// ---------------- fp32 -> (hi,lo) bf16 split ----------------
__global__ void cvt_split(const float* __restrict__ in, bf16* __restrict__ hi,
                          bf16* __restrict__ lo, long long n4)
{
    long long i = blockIdx.x * (long long)blockDim.x + threadIdx.x;
    if (i >= n4) return;
    float4 v = reinterpret_cast<const float4*>(in)[i];
    bf16 h0 = bhi(v.x), h1 = bhi(v.y), h2 = bhi(v.z), h3 = bhi(v.w);
    __nv_bfloat162 a = __halves2bfloat162(h0, h1), b = __halves2bfloat162(h2, h3);
    __nv_bfloat162 c = __halves2bfloat162(blo(v.x, h0), blo(v.y, h1));
    __nv_bfloat162 d = __halves2bfloat162(blo(v.z, h2), blo(v.w, h3));
    reinterpret_cast<uint2*>(hi)[i] = make_uint2(*(uint32_t*)&a, *(uint32_t*)&b);
    reinterpret_cast<uint2*>(lo)[i] = make_uint2(*(uint32_t*)&c, *(uint32_t*)&d);
}

// ---------------- score_c transpose + split ----------------
__global__ void transpose_split(const float* __restrict__ in,
                                bf16* __restrict__ oh, bf16* __restrict__ ol)
{
    __shared__ float tile[32][33];
    const int b = blockIdx.z;
    const int x0 = blockIdx.x << 5;   // T1
    const int y0 = blockIdx.y << 5;   // TC
    const float* ib = in + (long long)b * TC * T1;
    const int tx = threadIdx.x, ty = threadIdx.y;
    #pragma unroll
    for (int i = 0; i < 4; i++)
        tile[ty + 8*i][tx] = ib[(long long)(y0 + ty + 8*i) * T1 + x0 + tx];
    __syncthreads();
    bf16* ohb = oh + (long long)b * T1 * TC;
    bf16* olb = ol + (long long)b * T1 * TC;
    #pragma unroll
    for (int i = 0; i < 4; i++) {
        float v = tile[tx][ty + 8*i];
        bf16 h = bhi(v);
        long long o = (long long)(x0 + ty + 8*i) * TC + y0 + tx;
        ohb[o] = h;
        olb[o] = blo(v, h);
    }
}

// ---------------- reductions ----------------
__device__ __forceinline__ float warpMax(float v) {
    #pragma unroll
    for (int o = 16; o > 0; o >>= 1) v = fmaxf(v, __shfl_xor_sync(0xffffffffu, v, o));
    return v;
}
__device__ __forceinline__ float warpSum(float v) {
    #pragma unroll
    for (int o = 16; o > 0; o >>= 1) v += __shfl_xor_sync(0xffffffffu, v, o);
    return v;
}
__device__ __forceinline__ float blockMax(float v) {
    __shared__ float sh[8];
    v = warpMax(v);
    __syncthreads();
    if ((threadIdx.x & 31) == 0) sh[threadIdx.x >> 5] = v;
    __syncthreads();
    float r = -1e30f;
    int nw = blockDim.x >> 5;
    #pragma unroll
    for (int i = 0; i < 8; i++) if (i < nw) r = fmaxf(r, sh[i]);
    return r;
}
__device__ __forceinline__ float blockSum(float v) {
    __shared__ float sh[8];
    v = warpSum(v);
    __syncthreads();
    if ((threadIdx.x & 31) == 0) sh[threadIdx.x >> 5] = v;
    __syncthreads();
    float r = 0.0f;
    int nw = blockDim.x >> 5;
    #pragma unroll
    for (int i = 0; i < 8; i++) if (i < nw) r += sh[i];
    return r;
}

// ---------------- dual softmax + blend -> hi/lo ----------------
__global__ void __launch_bounds__(256)
softmax_blend(const float* __restrict__ mixed, const float* __restrict__ att,
              bf16* __restrict__ oh, bf16* __restrict__ ol)
{
    const long long base = (long long)blockIdx.x * T1;
    const int tid = threadIdx.x;
    float mv[8], av[8];
    float m1 = -1e30f, m2 = -1e30f;
    #pragma unroll
    for (int i = 0; i < 8; i++) {
        int c = tid + i * 256;
        mv[i] = mixed[base + c];
        av[i] = att[base + c];
        m1 = fmaxf(m1, mv[i]);
        m2 = fmaxf(m2, av[i]);
    }
    m1 = blockMax(m1);
    m2 = blockMax(m2);
    float s1 = 0.f, s2 = 0.f;
    #pragma unroll
    for (int i = 0; i < 8; i++) {
        mv[i] = __expf(mv[i] - m1);
        av[i] = __expf(av[i] - m2);
        s1 += mv[i]; s2 += av[i];
    }
    s1 = blockSum(s1);
    s2 = blockSum(s2);
    const float r1 = TTMIX / s1, r2 = (1.0f - TTMIX) / s2;
    #pragma unroll
    for (int i = 0; i < 8; i++) {
        int c = tid + i * 256;
        float v = mv[i] * r1 + av[i] * r2;
        bf16 h = bhi(v);
        oh[base + c] = h;
        ol[base + c] = blo(v, h);
    }
}

// ---------------- residual add + LayerNorm -> fp32 + hi/lo ----------------
__global__ void __launch_bounds__(128)
add_ln(float* __restrict__ x, const float* __restrict__ z,
       const float* __restrict__ g, const float* __restrict__ b,
       bf16* __restrict__ xh, bf16* __restrict__ xl)
{
    const long long base = (long long)blockIdx.x * D_;
    const int tid = threadIdx.x;
    float v[3];
    #pragma unroll
    for (int i = 0; i < 3; i++) v[i] = x[base + tid + i*128] + z[base + tid + i*128];
    float s = v[0] + v[1] + v[2];
    s = blockSum(s);
    const float mean = s * (1.0f / D_);
    float q = 0.f;
    #pragma unroll
    for (int i = 0; i < 3; i++) { float d = v[i] - mean; q += d * d; }
    q = blockSum(q);
    const float rstd = rsqrtf(q * (1.0f / D_) + LN_EPS);
    #pragma unroll
    for (int i = 0; i < 3; i++) {
        int c = tid + i * 128;
        float o = (v[i] - mean) * rstd * g[c] + b[c];
        x[base + c] = o;
        bf16 h = bhi(o);
        xh[base + c] = h;
        xl[base + c] = blo(o, h);
    }
}

// ---------------- host ----------------
#define SMEM_DYN (STAGES * STAGE_BYTES)
#define SYM(p, s) do { void* _t; cudaGetSymbolAddress(&_t, s); p = (decltype(p))_t; } while (0)

static void split(const float* in, bf16* hi, bf16* lo, long long n) {
    long long n4 = n / 4;
    cvt_split<<<(unsigned)((n4 + 255) / 256), 256>>>(in, hi, lo, n4);
}
static void gemm(const bf16* Ah, const bf16* Al, const bf16* Bh, const bf16* Bl,
                 const float* bias, float alpha, int flags,
                 float* Cf, bf16* Ch, bf16* Cl,
                 int M, int N, int K, int batch,
                 long long sA, long long sB, long long sC) {
    dim3 g(N / 128, M / 128, batch);
    mma_gemm<<<g, 256, SMEM_DYN>>>(Ah, Al, Bh, Bl, bias, alpha, flags,
                                   Cf, Ch, Cl, M, N, K, sA, sB, sC);
}

extern "C" void kernel_launch(void* const* d_in, const int* in_sizes, int n_in,
                              void* d_out, int out_size)
{
    (void)in_sizes; (void)n_in; (void)out_size;
    const float* tgt     = (const float*)d_in[0];
    const float* memory  = (const float*)d_in[1];
    const float* score_c = (const float*)d_in[2];
    const float* out_c   = (const float*)d_in[3];
    const float* Wq  = (const float*)d_in[4];
    const float* bq  = (const float*)d_in[5];
    const float* Wk  = (const float*)d_in[6];
    const float* bk  = (const float*)d_in[7];
    const float* Wv  = (const float*)d_in[8];
    const float* bv  = (const float*)d_in[9];
    const float* Wkn = (const float*)d_in[10];
    const float* bkn = (const float*)d_in[11];
    const float* Wun = (const float*)d_in[12];
    const float* bun = (const float*)d_in[13];
    const float* W1  = (const float*)d_in[14];
    const float* b1  = (const float*)d_in[15];
    const float* W2  = (const float*)d_in[16];
    const float* b2  = (const float*)d_in[17];
    const float* g1  = (const float*)d_in[18];
    const float* be1 = (const float*)d_in[19];
    const float* g2  = (const float*)d_in[20];
    const float* be2 = (const float*)d_in[21];

    float *x, *att, *mix, *z;
    SYM(x, g_x); SYM(att, g_att); SYM(mix, g_mix); SYM(z, g_z);
    bf16 *xh,*xl,*qh,*ql,*kh,*kl,*vth,*vtl,*unh,*unl,*knh,*knl,*s1h,*s1l,*blh,*bll,*hh,*hl;
    bf16 *mh,*ml,*oh,*ol,*sth,*stl;
    bf16 *wqh,*wql,*wkh,*wkl,*wvh,*wvl,*wnh,*wnl,*wuh,*wul,*w1h,*w1l,*w2h,*w2l;
    SYM(xh,g_xh); SYM(xl,g_xl); SYM(qh,g_qh); SYM(ql,g_ql);
    SYM(kh,g_kh); SYM(kl,g_kl); SYM(vth,g_vth); SYM(vtl,g_vtl);
    SYM(unh,g_unh); SYM(unl,g_unl); SYM(knh,g_knh); SYM(knl,g_knl);
    SYM(s1h,g_s1h); SYM(s1l,g_s1l); SYM(blh,g_blh); SYM(bll,g_bll);
    SYM(hh,g_hh); SYM(hl,g_hl); SYM(mh,g_mh); SYM(ml,g_ml);
    SYM(oh,g_oh); SYM(ol,g_ol); SYM(sth,g_sth); SYM(stl,g_stl);
    SYM(wqh,g_wqh); SYM(wql,g_wql); SYM(wkh,g_wkh); SYM(wkl,g_wkl);
    SYM(wvh,g_wvh); SYM(wvl,g_wvl); SYM(wnh,g_wnh); SYM(wnl,g_wnl);
    SYM(wuh,g_wuh); SYM(wul,g_wul);
    SYM(w1h,g_w1h); SYM(w1l,g_w1l); SYM(w2h,g_w2h); SYM(w2l,g_w2l);

    cudaFuncSetAttribute(mma_gemm, cudaFuncAttributeMaxDynamicSharedMemorySize, SMEM_DYN);

    const float scale = 1.0f / sqrtf((float)D_);

    // one-time conversions
    cudaMemcpyAsync(x, tgt, (size_t)NX * 4, cudaMemcpyDeviceToDevice);
    split(tgt, xh, xl, NX);
    split(memory, mh, ml, NMEM);
    split(out_c, oh, ol, NOC);
    split(Wq, wqh, wql, NWQ);
    split(Wk, wkh, wkl, NWK);
    split(Wv, wvh, wvl, NWK);
    split(Wkn, wnh, wnl, NWQ);
    split(Wun, wuh, wul, NWQ);
    split(W1, w1h, w1l, NW1);
    split(W2, w2h, w2l, NW1);

    for (int l = 0; l < LY; l++) {
        const long long oq = (long long)l * D_ * D_;
        const long long ok = (long long)l * D_ * DK;
        const long long o1 = (long long)l * FF * D_;
        // q = x @ Wq^T + bq
        gemm(xh, xl, wqh + oq, wql + oq, bq + l*D_, 1.f, 0, nullptr, qh, ql,
             BN*T_, D_, D_, 1, 0, 0, 0);
        // k = memory @ Wk^T + bk
        gemm(mh, ml, wkh + ok, wkl + ok, bk + l*D_, 1.f, 0, nullptr, kh, kl,
             BN*T1, D_, DK, 1, 0, 0, 0);
        // vT_b = Wv @ memory_b^T + bv (row bias)
        gemm(wvh + ok, wvl + ok, mh, ml, bv + l*D_, 1.f, 2, nullptr, vth, vtl,
             D_, T1, DK, BN, 0, (long long)T1*DK, (long long)D_*T1);
        // att = scale * q_b @ k_b^T
        gemm(qh, ql, kh, kl, nullptr, scale, 0, att, nullptr, nullptr,
             T_, T1, D_, BN, (long long)T_*D_, (long long)T1*D_, (long long)T_*T1);
        // unk = x @ Wun^T + bun
        gemm(xh, xl, wuh + oq, wul + oq, bun + l*D_, 1.f, 0, nullptr, unh, unl,
             BN*T_, D_, D_, 1, 0, 0, 0);
        // knoT_b = Wkn @ out_c_b^T + bkn (row bias): [D, TC] per batch
        gemm(wnh + oq, wnl + oq,
             oh + (long long)l*BN*TC*D_, ol + (long long)l*BN*TC*D_,
             bkn + l*D_, 1.f, 2, nullptr, knh, knl,
             D_, TC, D_, BN, 0, (long long)TC*D_, (long long)D_*TC);
        // score_c[l]^T (+split) -> sth [B, T1, TC]
        {
            dim3 g(T1/32, TC/32, BN), b(32, 8);
            transpose_split<<<g, b>>>(score_c + (long long)l*BN*TC*T1, sth, stl);
        }
        // M2T_b = scale * sth_b @ knoT_b^T : [T1, D] per batch (into s1h/s1l)
        gemm(sth, stl, knh, knl, nullptr, scale, 0, nullptr, s1h, s1l,
             T1, D_, TC, BN, (long long)T1*TC, (long long)D_*TC, (long long)T1*D_);
        // mixed_b = unk_b @ M2T_b^T : [T, T1]
        gemm(unh, unl, s1h, s1l, nullptr, 1.f, 0, mix, nullptr, nullptr,
             T_, T1, D_, BN, (long long)T_*D_, (long long)T1*D_, (long long)T_*T1);
        // blended = TT*softmax(mixed) + (1-TT)*softmax(att)
        softmax_blend<<<BN*T_, 256>>>(mix, att, blh, bll);
        // z = blended_b @ vT_b^T
        gemm(blh, bll, vth, vtl, nullptr, 1.f, 0, z, nullptr, nullptr,
             T_, D_, T1, BN, (long long)T_*T1, (long long)D_*T1, (long long)T_*D_);
        // x = LN(x + z)
        add_ln<<<BN*T_, 128>>>(x, z, g1 + l*D_, be1 + l*D_, xh, xl);
        // h = relu(x @ W1^T + b1)
        gemm(xh, xl, w1h + o1, w1l + o1, b1 + l*FF, 1.f, 1, nullptr, hh, hl,
             BN*T_, FF, D_, 1, 0, 0, 0);
        // y2 = h @ W2^T + b2  (into z)
        gemm(hh, hl, w2h + o1, w2l + o1, b2 + l*D_, 1.f, 0, z, nullptr, nullptr,
             BN*T_, D_, FF, 1, 0, 0, 0);
        // x = LN(x + y2)
        add_ln<<<BN*T_, 128>>>(x, z, g2 + l*D_, be2 + l*D_, xh, xl);
    }

    cudaMemcpyAsync(d_out, x, (size_t)NX * 4, cudaMemcpyDeviceToDevice);
}

// round 5
// speedup vs baseline: 3.6383x; 1.1146x over previous
#include <cuda_runtime.h>
#include <cuda_bf16.h>
#include <math.h>
#include <stdint.h>

typedef __nv_bfloat16 bf16;

// ---------------- problem dims ----------------
#define LY 4
#define BN 4
#define T_ 1024
#define TC 1024
#define T1 2048
#define D_ 384
#define DK 256
#define FF 1536
#define TTMIX 0.1f
#define LN_EPS 1e-5f

#define NX   (BN*T_*D_)
#define NAT  (BN*T_*T1)
#define NQX  (BN*T_*DK)
#define NH_  (BN*T_*FF)
#define NMEM (BN*T1*DK)
#define NOC  (LY*BN*TC*D_)
#define NSCT (BN*T1*TC)
#define NM2  (BN*T1*D_)
#define NWQT (LY*D_*D_)
#define NWKT (LY*D_*DK)
#define NW1  (LY*FF*D_)

// ---------------- scratch ----------------
__device__ __align__(128) float g_x[NX], g_att[NAT], g_mix[NAT], g_z[NX];
__device__ __align__(128) float g_pvec[DK], g_wvec[BN*T1];
__device__ __align__(128) bf16 g_xh[NX], g_xl[NX], g_qxh[NQX], g_qxl[NQX];
__device__ __align__(128) bf16 g_mh[NMEM], g_ml[NMEM], g_mth[NMEM], g_mtl[NMEM];
__device__ __align__(128) bf16 g_unh[NX], g_unl[NX], g_knh[NX], g_knl[NX];
__device__ __align__(128) bf16 g_s1h[NM2], g_s1l[NM2], g_blh[NAT], g_bll[NAT];
__device__ __align__(128) bf16 g_hh[NH_], g_hl[NH_];
__device__ __align__(128) bf16 g_oh[NOC], g_ol[NOC], g_sth[NSCT], g_stl[NSCT];
__device__ __align__(128) bf16 g_wqth[NWQT], g_wqtl[NWQT];
__device__ __align__(128) bf16 g_wkth[NWKT], g_wktl[NWKT];
__device__ __align__(128) bf16 g_wqkth[NWKT], g_wqktl[NWKT];
__device__ __align__(128) bf16 g_wvh[NWKT], g_wvl[NWKT];
__device__ __align__(128) bf16 g_wnh[NWQT], g_wnl[NWQT];
__device__ __align__(128) bf16 g_wuh[NWQT], g_wul[NWQT];
__device__ __align__(128) bf16 g_w1h[NW1], g_w1l[NW1], g_w2h[NW1], g_w2l[NW1];

// ---------------- helpers ----------------
__device__ __forceinline__ uint32_t u32smem(const void* p) {
    uint32_t a;
    asm("{ .reg .u64 t; cvta.to.shared.u64 t, %1; cvt.u32.u64 %0, t; }" : "=r"(a) : "l"(p));
    return a;
}
__device__ __forceinline__ void cpa16(uint32_t s, const void* g) {
    asm volatile("cp.async.cg.shared.global [%0], [%1], 16;" :: "r"(s), "l"(g));
}
#define CP_COMMIT() asm volatile("cp.async.commit_group;" ::: "memory")
#define CP_WAIT(n)  asm volatile("cp.async.wait_group %0;" :: "n"(n) : "memory")

__device__ __forceinline__ void ldsm_x4(uint32_t& r0, uint32_t& r1, uint32_t& r2,
                                        uint32_t& r3, uint32_t a) {
    asm volatile("ldmatrix.sync.aligned.m8n8.x4.shared.b16 {%0,%1,%2,%3}, [%4];"
                 : "=r"(r0), "=r"(r1), "=r"(r2), "=r"(r3) : "r"(a));
}
__device__ __forceinline__ void mma16816(float* d, const uint32_t* a, const uint32_t* b) {
    asm volatile(
        "mma.sync.aligned.m16n8k16.row.col.f32.bf16.bf16.f32 "
        "{%0,%1,%2,%3},{%4,%5,%6,%7},{%8,%9},{%0,%1,%2,%3};"
        : "+f"(d[0]), "+f"(d[1]), "+f"(d[2]), "+f"(d[3])
        : "r"(a[0]), "r"(a[1]), "r"(a[2]), "r"(a[3]), "r"(b[0]), "r"(b[1]));
}
__device__ __forceinline__ bf16 bhi(float x) { return __float2bfloat16(x); }
__device__ __forceinline__ bf16 blo(float x, bf16 h) { return __float2bfloat16(x - __bfloat162float(h)); }

// ---------------- split-bf16 tensor GEMM: C = alpha*A@B^T (+bias)(+relu) -----
// A:[M,K] hi/lo, B:[N,K] hi/lo (K-major). CTA 128x128, BK=32, 3-stage cp.async,
// 2 CTAs/SM. flags: 1=relu, 2=bias by row (else col).
// Split-K: blockIdx.z = batch*kspl + ks; each ks covers K/kspl; if kspl>1,
// partials (fp32) go to Cf + ks*slabStride (caller passes bias=null, Ch=null).
#define STAGES 3
#define STAGE_BYTES 32768

__global__ void __launch_bounds__(256, 2)
mma_gemm(const bf16* __restrict__ Ah, const bf16* __restrict__ Al,
         const bf16* __restrict__ Bh, const bf16* __restrict__ Bl,
         const float* __restrict__ bias, float alpha, int flags,
         float* __restrict__ Cf, bf16* __restrict__ Ch, bf16* __restrict__ Cl,
         int M, int N, int K, long long sA, long long sB, long long sC,
         int kspl, long long slabStride)
{
    extern __shared__ char sm[];
    const int tid = threadIdx.x, lane = tid & 31, wid = tid >> 5;
    const int wm = wid & 3, wn = wid >> 2;          // warp tile 32(m) x 64(n)
    const int zb = blockIdx.z;
    const long long bz = zb / kspl;
    const int ks = zb - (int)bz * kspl;
    const int Kc = K / kspl;
    const int bm0 = blockIdx.y << 7, bn0 = blockIdx.x << 7;

    const char* gsrc[4] = {
        (const char*)(Ah + bz * sA + (long long)bm0 * K),
        (const char*)(Al + bz * sA + (long long)bm0 * K),
        (const char*)(Bh + bz * sB + (long long)bn0 * K),
        (const char*)(Bl + bz * sB + (long long)bn0 * K) };
    const uint32_t sbase = u32smem(sm);
    const long long rowbytes = (long long)K * 2;

    float acc[2][8][4];
    #pragma unroll
    for (int i = 0; i < 2; i++)
        #pragma unroll
        for (int j = 0; j < 8; j++)
            #pragma unroll
            for (int q = 0; q < 4; q++) acc[i][j][q] = 0.f;

    const int nc = Kc >> 5;
    const int kbase = ks * Kc;

    auto load_stage = [&](int buf, int k0) {
        uint32_t sb = sbase + buf * STAGE_BYTES;
        #pragma unroll
        for (int t = 0; t < 4; t++) {
            uint32_t ab = sb + t * 8192;
            const char* g = gsrc[t];
            #pragma unroll
            for (int i = 0; i < 2; i++) {
                int idx = i * 256 + tid;
                int r = idx >> 2, c = idx & 3;
                uint32_t so = ab + r * 64 + ((c ^ ((r >> 1) & 3)) << 4);
                cpa16(so, g + (long long)r * rowbytes + (long long)k0 * 2 + c * 16);
            }
        }
    };

    auto compute = [&](int buf) {
        uint32_t sb = sbase + buf * STAGE_BYTES;
        #pragma unroll
        for (int s = 0; s < 2; s++) {
            uint32_t a_h[2][4], a_l[2][4];
            #pragma unroll
            for (int mi = 0; mi < 2; mi++) {
                int row = wm * 32 + mi * 16 + (lane & 15);
                int kc  = 2 * s + (lane >> 4);
                uint32_t off = row * 64 + ((kc ^ ((row >> 1) & 3)) << 4);
                ldsm_x4(a_h[mi][0], a_h[mi][1], a_h[mi][2], a_h[mi][3], sb + off);
                ldsm_x4(a_l[mi][0], a_l[mi][1], a_l[mi][2], a_l[mi][3], sb + 8192 + off);
            }
            #pragma unroll
            for (int nj = 0; nj < 4; nj++) {
                int row = wn * 64 + nj * 16 + (lane & 15);
                int kc  = 2 * s + (lane >> 4);
                uint32_t off = row * 64 + ((kc ^ ((row >> 1) & 3)) << 4);
                uint32_t h0, h1, h2, h3, l0, l1, l2, l3;
                ldsm_x4(h0, h1, h2, h3, sb + 16384 + off);
                ldsm_x4(l0, l1, l2, l3, sb + 24576 + off);
                uint32_t bh0[2] = {h0, h2}, bh1[2] = {h1, h3};
                uint32_t bl0[2] = {l0, l2}, bl1[2] = {l1, l3};
                #pragma unroll
                for (int mi = 0; mi < 2; mi++) {
                    mma16816(acc[mi][2*nj],   a_h[mi], bh0);
                    mma16816(acc[mi][2*nj],   a_h[mi], bl0);
                    mma16816(acc[mi][2*nj],   a_l[mi], bh0);
                    mma16816(acc[mi][2*nj+1], a_h[mi], bh1);
                    mma16816(acc[mi][2*nj+1], a_h[mi], bl1);
                    mma16816(acc[mi][2*nj+1], a_l[mi], bh1);
                }
            }
        }
    };

    #pragma unroll
    for (int s = 0; s < STAGES - 1; s++) {
        if (s < nc) load_stage(s, kbase + s * 32);
        CP_COMMIT();
    }
    int buf = 0, nxt = STAGES - 1;
    for (int c = 0; c < nc; c++) {
        CP_WAIT(STAGES - 2);
        __syncthreads();
        if (c + STAGES - 1 < nc) {
            load_stage(nxt, kbase + (c + STAGES - 1) * 32);
            CP_COMMIT();
        } else {
            CP_COMMIT();
        }
        compute(buf);
        if (++buf == STAGES) buf = 0;
        if (++nxt == STAGES) nxt = 0;
    }

    // ---- epilogue ----
    float* Cfo = Cf ? Cf + (long long)ks * slabStride : nullptr;
    const int rl = lane >> 2, cl = (lane & 3) * 2;
    #pragma unroll
    for (int mi = 0; mi < 2; mi++) {
        #pragma unroll
        for (int hf = 0; hf < 2; hf++) {
            const long long grow = bm0 + wm * 32 + mi * 16 + rl + hf * 8;
            float brow = 0.f;
            if (bias && (flags & 2)) brow = bias[grow];
            const long long base = bz * sC + grow * (long long)N + bn0 + wn * 64;
            #pragma unroll
            for (int nb = 0; nb < 8; nb++) {
                const int coff = nb * 8 + cl;
                float v0 = acc[mi][nb][hf*2+0] * alpha;
                float v1 = acc[mi][nb][hf*2+1] * alpha;
                if (bias) {
                    if (flags & 2) { v0 += brow; v1 += brow; }
                    else {
                        const long long gcol = bn0 + wn * 64 + coff;
                        v0 += bias[gcol]; v1 += bias[gcol + 1];
                    }
                }
                if (flags & 1) { v0 = fmaxf(v0, 0.f); v1 = fmaxf(v1, 0.f); }
                if (Cfo) *reinterpret_cast<float2*>(Cfo + base + coff) = make_float2(v0, v1);
                if (Ch) {
                    bf16 h0 = bhi(v0), h1 = bhi(v1);
                    __nv_bfloat162 hh = __halves2bfloat162(h0, h1);
                    __nv_bfloat162 ll = __halves2bfloat162(blo(v0, h0), blo(v1, h1));
                    *reinterpret_cast<uint32_t*>(Ch + base + coff) = *reinterpret_cast<uint32_t*>(&hh);
                    *reinterpret_cast<uint32_t*>(Cl + base + coff) = *reinterpret_cast<uint32_t*>(&ll);
                }
            }
        }
    }
}

// ---------------- fp32 -> (hi,lo) bf16 split ----------------
__global__ void cvt_split(const float* __restrict__ in, bf16* __restrict__ hi,
                          bf16* __restrict__ lo, long long n4)
{
    long long i = blockIdx.x * (long long)blockDim.x + threadIdx.x;
    if (i >= n4) return;
    float4 v = reinterpret_cast<const float4*>(in)[i];
    bf16 h0 = bhi(v.x), h1 = bhi(v.y), h2 = bhi(v.z), h3 = bhi(v.w);
    __nv_bfloat162 a = __halves2bfloat162(h0, h1), b = __halves2bfloat162(h2, h3);
    __nv_bfloat162 c = __halves2bfloat162(blo(v.x, h0), blo(v.y, h1));
    __nv_bfloat162 d = __halves2bfloat162(blo(v.z, h2), blo(v.w, h3));
    reinterpret_cast<uint2*>(hi)[i] = make_uint2(*(uint32_t*)&a, *(uint32_t*)&b);
    reinterpret_cast<uint2*>(lo)[i] = make_uint2(*(uint32_t*)&c, *(uint32_t*)&d);
}

// ---------------- sum ns slabs (fp32) -> hi/lo bf16 ----------------
__global__ void reduce_split(const float* __restrict__ slabs, long long sstride4,
                             int ns, bf16* __restrict__ hi, bf16* __restrict__ lo,
                             long long n4)
{
    long long i = blockIdx.x * (long long)blockDim.x + threadIdx.x;
    if (i >= n4) return;
    const float4* p = reinterpret_cast<const float4*>(slabs);
    float4 v = p[i];
    for (int s = 1; s < ns; s++) {
        float4 t = p[i + s * sstride4];
        v.x += t.x; v.y += t.y; v.z += t.z; v.w += t.w;
    }
    bf16 h0 = bhi(v.x), h1 = bhi(v.y), h2 = bhi(v.z), h3 = bhi(v.w);
    __nv_bfloat162 a = __halves2bfloat162(h0, h1), b = __halves2bfloat162(h2, h3);
    __nv_bfloat162 c = __halves2bfloat162(blo(v.x, h0), blo(v.y, h1));
    __nv_bfloat162 d = __halves2bfloat162(blo(v.z, h2), blo(v.w, h3));
    reinterpret_cast<uint2*>(hi)[i] = make_uint2(*(uint32_t*)&a, *(uint32_t*)&b);
    reinterpret_cast<uint2*>(lo)[i] = make_uint2(*(uint32_t*)&c, *(uint32_t*)&d);
}

// ---------------- generic transpose+split: [batch,R,C] f32 -> [batch,C,R] hi/lo
__global__ void transpose_split_g(const float* __restrict__ in,
                                  bf16* __restrict__ oh, bf16* __restrict__ ol,
                                  int R, int C)
{
    __shared__ float tile[32][33];
    const long long b = blockIdx.z;
    const int c0 = blockIdx.x << 5;
    const int r0 = blockIdx.y << 5;
    const float* ib = in + b * (long long)R * C;
    const int tx = threadIdx.x, ty = threadIdx.y;
    #pragma unroll
    for (int i = 0; i < 4; i++)
        tile[ty + 8*i][tx] = ib[(long long)(r0 + ty + 8*i) * C + c0 + tx];
    __syncthreads();
    bf16* ohb = oh + b * (long long)R * C;
    bf16* olb = ol + b * (long long)R * C;
    #pragma unroll
    for (int i = 0; i < 4; i++) {
        float v = tile[tx][ty + 8*i];
        bf16 h = bhi(v);
        long long o = (long long)(c0 + ty + 8*i) * R + r0 + tx;
        ohb[o] = h;
        olb[o] = blo(v, h);
    }
}

// ---------------- bias-fold vectors for att path ----------------
__global__ void pvec_k(const float* __restrict__ Wk, const float* __restrict__ bq,
                       float* __restrict__ pvec)
{
    int dk = threadIdx.x;            // DK threads
    float s = 0.f;
    for (int e = 0; e < D_; e++) s += bq[e] * Wk[(long long)e * DK + dk];
    pvec[dk] = s;
}
__global__ void wvec_k(const float* __restrict__ mem, const float* __restrict__ pvec,
                       float* __restrict__ w, float scale)
{
    int i = blockIdx.x * 256 + threadIdx.x;   // BN*T1 threads
    const float* m = mem + (long long)i * DK;
    float s = 0.f;
    #pragma unroll 8
    for (int dk = 0; dk < DK; dk++) s += m[dk] * pvec[dk];
    w[i] = s * scale;
}

// ---------------- reductions ----------------
__device__ __forceinline__ float warpMax(float v) {
    #pragma unroll
    for (int o = 16; o > 0; o >>= 1) v = fmaxf(v, __shfl_xor_sync(0xffffffffu, v, o));
    return v;
}
__device__ __forceinline__ float warpSum(float v) {
    #pragma unroll
    for (int o = 16; o > 0; o >>= 1) v += __shfl_xor_sync(0xffffffffu, v, o);
    return v;
}
__device__ __forceinline__ float blockMax(float v) {
    __shared__ float sh[8];
    v = warpMax(v);
    __syncthreads();
    if ((threadIdx.x & 31) == 0) sh[threadIdx.x >> 5] = v;
    __syncthreads();
    float r = -1e30f;
    int nw = blockDim.x >> 5;
    #pragma unroll
    for (int i = 0; i < 8; i++) if (i < nw) r = fmaxf(r, sh[i]);
    return r;
}
__device__ __forceinline__ float blockSum(float v) {
    __shared__ float sh[8];
    v = warpSum(v);
    __syncthreads();
    if ((threadIdx.x & 31) == 0) sh[threadIdx.x >> 5] = v;
    __syncthreads();
    float r = 0.0f;
    int nw = blockDim.x >> 5;
    #pragma unroll
    for (int i = 0; i < 8; i++) if (i < nw) r += sh[i];
    return r;
}

// ---------------- dual softmax + blend (att gets +w[s]) -> hi/lo -------------
__global__ void __launch_bounds__(256)
softmax_blend(const float* __restrict__ mixed, const float* __restrict__ att,
              const float* __restrict__ w,
              bf16* __restrict__ oh, bf16* __restrict__ ol)
{
    const long long base = (long long)blockIdx.x * T1;
    const int b = blockIdx.x >> 10;   // T_ = 1024
    const int tid = threadIdx.x;
    float mv[8], av[8];
    float m1 = -1e30f, m2 = -1e30f;
    #pragma unroll
    for (int i = 0; i < 8; i++) {
        int c = tid + i * 256;
        mv[i] = mixed[base + c];
        av[i] = att[base + c] + w[(long long)b * T1 + c];
        m1 = fmaxf(m1, mv[i]);
        m2 = fmaxf(m2, av[i]);
    }
    m1 = blockMax(m1);
    m2 = blockMax(m2);
    float s1 = 0.f, s2 = 0.f;
    #pragma unroll
    for (int i = 0; i < 8; i++) {
        mv[i] = __expf(mv[i] - m1);
        av[i] = __expf(av[i] - m2);
        s1 += mv[i]; s2 += av[i];
    }
    s1 = blockSum(s1);
    s2 = blockSum(s2);
    const float r1 = TTMIX / s1, r2 = (1.0f - TTMIX) / s2;
    #pragma unroll
    for (int i = 0; i < 8; i++) {
        int c = tid + i * 256;
        float v = mv[i] * r1 + av[i] * r2;
        bf16 h = bhi(v);
        oh[base + c] = h;
        ol[base + c] = blo(v, h);
    }
}

// ---------------- residual add (x + sum slabs + bias2) + LayerNorm -----------
__global__ void __launch_bounds__(128)
add_ln(float* __restrict__ x, const float* __restrict__ slabs, int ns,
       long long sstride, const float* __restrict__ bias2,
       const float* __restrict__ g, const float* __restrict__ b,
       bf16* __restrict__ xh, bf16* __restrict__ xl)
{
    const long long base = (long long)blockIdx.x * D_;
    const int tid = threadIdx.x;
    float v[3];
    #pragma unroll
    for (int i = 0; i < 3; i++) {
        int c = tid + i * 128;
        float t = x[base + c];
        for (int s = 0; s < ns; s++) t += slabs[s * sstride + base + c];
        if (bias2) t += bias2[c];
        v[i] = t;
    }
    float s = v[0] + v[1] + v[2];
    s = blockSum(s);
    const float mean = s * (1.0f / D_);
    float q = 0.f;
    #pragma unroll
    for (int i = 0; i < 3; i++) { float d = v[i] - mean; q += d * d; }
    q = blockSum(q);
    const float rstd = rsqrtf(q * (1.0f / D_) + LN_EPS);
    #pragma unroll
    for (int i = 0; i < 3; i++) {
        int c = tid + i * 128;
        float o = (v[i] - mean) * rstd * g[c] + b[c];
        x[base + c] = o;
        bf16 h = bhi(o);
        xh[base + c] = h;
        xl[base + c] = blo(o, h);
    }
}

// ---------------- host ----------------
#define SMEM_DYN (STAGES * STAGE_BYTES)
#define SYM(p, s) do { void* _t; cudaGetSymbolAddress(&_t, s); p = (decltype(p))_t; } while (0)

static void split(const float* in, bf16* hi, bf16* lo, long long n) {
    long long n4 = n / 4;
    cvt_split<<<(unsigned)((n4 + 255) / 256), 256>>>(in, hi, lo, n4);
}
static void gemm(const bf16* Ah, const bf16* Al, const bf16* Bh, const bf16* Bl,
                 const float* bias, float alpha, int flags,
                 float* Cf, bf16* Ch, bf16* Cl,
                 int M, int N, int K, int batch,
                 long long sA, long long sB, long long sC,
                 int kspl = 1, long long slabStride = 0) {
    dim3 g(N / 128, M / 128, batch * kspl);
    mma_gemm<<<g, 256, SMEM_DYN>>>(Ah, Al, Bh, Bl, bias, alpha, flags,
                                   Cf, Ch, Cl, M, N, K, sA, sB, sC,
                                   kspl, slabStride);
}
static void transpose_split(const float* in, bf16* oh, bf16* ol,
                            int R, int C, int batch) {
    dim3 g(C / 32, R / 32, batch), b(32, 8);
    transpose_split_g<<<g, b>>>(in, oh, ol, R, C);
}

extern "C" void kernel_launch(void* const* d_in, const int* in_sizes, int n_in,
                              void* d_out, int out_size)
{
    (void)in_sizes; (void)n_in; (void)out_size;
    const float* tgt     = (const float*)d_in[0];
    const float* memory  = (const float*)d_in[1];
    const float* score_c = (const float*)d_in[2];
    const float* out_c   = (const float*)d_in[3];
    const float* Wq  = (const float*)d_in[4];
    const float* bq  = (const float*)d_in[5];
    const float* Wk  = (const float*)d_in[6];
    const float* bk  = (const float*)d_in[7];  (void)bk; // shift-invariant under softmax
    const float* Wv  = (const float*)d_in[8];
    const float* bv  = (const float*)d_in[9];
    const float* Wkn = (const float*)d_in[10];
    const float* bkn = (const float*)d_in[11];
    const float* Wun = (const float*)d_in[12];
    const float* bun = (const float*)d_in[13];
    const float* W1  = (const float*)d_in[14];
    const float* b1  = (const float*)d_in[15];
    const float* W2  = (const float*)d_in[16];
    const float* b2  = (const float*)d_in[17];
    const float* g1  = (const float*)d_in[18];
    const float* be1 = (const float*)d_in[19];
    const float* g2  = (const float*)d_in[20];
    const float* be2 = (const float*)d_in[21];

    float *x, *att, *mix, *z, *pvec, *wvec;
    SYM(x, g_x); SYM(att, g_att); SYM(mix, g_mix); SYM(z, g_z);
    SYM(pvec, g_pvec); SYM(wvec, g_wvec);
    bf16 *xh,*xl,*qxh,*qxl,*mh,*ml,*mth,*mtl,*unh,*unl,*knh,*knl,*s1h,*s1l,*blh,*bll,*hh,*hl;
    bf16 *oh,*ol,*sth,*stl;
    bf16 *wqth,*wqtl,*wkth,*wktl,*wqkth,*wqktl,*wvh,*wvl,*wnh,*wnl,*wuh,*wul,*w1h,*w1l,*w2h,*w2l;
    SYM(xh,g_xh); SYM(xl,g_xl); SYM(qxh,g_qxh); SYM(qxl,g_qxl);
    SYM(mh,g_mh); SYM(ml,g_ml); SYM(mth,g_mth); SYM(mtl,g_mtl);
    SYM(unh,g_unh); SYM(unl,g_unl); SYM(knh,g_knh); SYM(knl,g_knl);
    SYM(s1h,g_s1h); SYM(s1l,g_s1l); SYM(blh,g_blh); SYM(bll,g_bll);
    SYM(hh,g_hh); SYM(hl,g_hl); SYM(oh,g_oh); SYM(ol,g_ol);
    SYM(sth,g_sth); SYM(stl,g_stl);
    SYM(wqth,g_wqth); SYM(wqtl,g_wqtl); SYM(wkth,g_wkth); SYM(wktl,g_wktl);
    SYM(wqkth,g_wqkth); SYM(wqktl,g_wqktl);
    SYM(wvh,g_wvh); SYM(wvl,g_wvl); SYM(wnh,g_wnh); SYM(wnl,g_wnl);
    SYM(wuh,g_wuh); SYM(wul,g_wul);
    SYM(w1h,g_w1h); SYM(w1l,g_w1l); SYM(w2h,g_w2h); SYM(w2l,g_w2l);

    cudaFuncSetAttribute(mma_gemm, cudaFuncAttributeMaxDynamicSharedMemorySize, SMEM_DYN);

    const float scale = 1.0f / sqrtf((float)D_);

    // ---- one-time prologue ----
    cudaMemcpyAsync(x, tgt, (size_t)NX * 4, cudaMemcpyDeviceToDevice);
    split(tgt, xh, xl, NX);
    split(memory, mh, ml, NMEM);
    split(out_c, oh, ol, NOC);
    split(Wv, wvh, wvl, NWKT);
    split(Wkn, wnh, wnl, NWQT);
    split(Wun, wuh, wul, NWQT);
    split(W1, w1h, w1l, NW1);
    split(W2, w2h, w2l, NW1);
    transpose_split(memory, mth, mtl, T1, DK, BN);           // memT [B,DK,T1]
    transpose_split(Wq, wqth, wqtl, D_, D_, LY);             // WqT  [L,D,D]
    transpose_split(Wk, wkth, wktl, D_, DK, LY);             // WkT  [L,DK,D]
    // Wqk^T[l] = WkT[l] @ WqT[l]^T : [DK, D] per layer
    gemm(wkth, wktl, wqth, wqtl, nullptr, 1.f, 0, nullptr, wqkth, wqktl,
         DK, D_, D_, LY, (long long)DK*D_, (long long)D_*D_, (long long)DK*D_);

    for (int l = 0; l < LY; l++) {
        const long long oq = (long long)l * D_ * D_;
        const long long ok = (long long)l * D_ * DK;
        const long long o1 = (long long)l * FF * D_;
        // att bias-fold vectors: w[b,s] = scale * mem[b,s,:]·(Wk^T bq)
        pvec_k<<<1, DK>>>(Wk + ok, bq + (long long)l*D_, pvec);
        wvec_k<<<BN*T1/256, 256>>>(memory, pvec, wvec, scale);
        // qx = x @ Wqk : [4096, DK]
        gemm(xh, xl, wqkth + ok, wqktl + ok, nullptr, 1.f, 0, nullptr, qxh, qxl,
             BN*T_, DK, D_, 1, 0, 0, 0);
        // att = scale * qx_b @ mem_b^T : [T, T1]
        gemm(qxh, qxl, mh, ml, nullptr, scale, 0, att, nullptr, nullptr,
             T_, T1, DK, BN, (long long)T_*DK, (long long)T1*DK, (long long)T_*T1);
        // unk = x @ Wun^T + bun
        gemm(xh, xl, wuh + oq, wul + oq, bun + (long long)l*D_, 1.f, 0,
             nullptr, unh, unl, BN*T_, D_, D_, 1, 0, 0, 0);
        // knoT_b = Wkn @ out_c_b^T + bkn (row bias): [D, TC]
        gemm(wnh + oq, wnl + oq,
             oh + (long long)l*BN*TC*D_, ol + (long long)l*BN*TC*D_,
             bkn + (long long)l*D_, 1.f, 2, nullptr, knh, knl,
             D_, TC, D_, BN, 0, (long long)TC*D_, (long long)D_*TC);
        // score_c[l]^T -> sth [B, T1, TC]
        transpose_split(score_c + (long long)l*BN*TC*T1, sth, stl, TC, T1, BN);
        // M2T_b = scale * sth_b @ knoT_b^T : [T1, D], split-K=2 -> slabs in mix
        gemm(sth, stl, knh, knl, nullptr, scale, 0, mix, nullptr, nullptr,
             T1, D_, TC, BN, (long long)T1*TC, (long long)D_*TC, (long long)T1*D_,
             2, (long long)NM2);
        reduce_split<<<(NM2/4 + 255)/256, 256>>>(mix, NM2/4, 2, s1h, s1l, NM2/4);
        // mixed_b = unk_b @ M2T_b^T : [T, T1]
        gemm(unh, unl, s1h, s1l, nullptr, 1.f, 0, mix, nullptr, nullptr,
             T_, T1, D_, BN, (long long)T_*D_, (long long)T1*D_, (long long)T_*T1);
        // blended = TT*softmax(mixed) + (1-TT)*softmax(att + w)
        softmax_blend<<<BN*T_, 256>>>(mix, att, wvec, blh, bll);
        // z1_b = blended_b @ memT_b^T : [T, DK], split-K=4 -> slabs in att
        gemm(blh, bll, mth, mtl, nullptr, 1.f, 0, att, nullptr, nullptr,
             T_, DK, T1, BN, (long long)T_*T1, (long long)DK*T1, (long long)T_*DK,
             4, (long long)NQX);
        reduce_split<<<(NQX/4 + 255)/256, 256>>>(att, NQX/4, 4, qxh, qxl, NQX/4);
        // z = z1 @ Wv^T + bv : [4096, D]
        gemm(qxh, qxl, wvh + ok, wvl + ok, bv + (long long)l*D_, 1.f, 0,
             z, nullptr, nullptr, BN*T_, D_, DK, 1, 0, 0, 0);
        // x = LN(x + z)
        add_ln<<<BN*T_, 128>>>(x, z, 1, 0, nullptr,
                               g1 + (long long)l*D_, be1 + (long long)l*D_, xh, xl);
        // h = relu(x @ W1^T + b1)
        gemm(xh, xl, w1h + o1, w1l + o1, b1 + (long long)l*FF, 1.f, 1,
             nullptr, hh, hl, BN*T_, FF, D_, 1, 0, 0, 0);
        // y2 = h @ W2^T, split-K=3 -> slabs in att; b2 added in add_ln
        gemm(hh, hl, w2h + o1, w2l + o1, nullptr, 1.f, 0, att, nullptr, nullptr,
             BN*T_, D_, FF, 1, 0, 0, 0, 3, (long long)NX);
        // x = LN(x + sum(slabs) + b2)
        add_ln<<<BN*T_, 128>>>(x, att, 3, (long long)NX, b2 + (long long)l*D_,
                               g2 + (long long)l*D_, be2 + (long long)l*D_, xh, xl);
    }

    cudaMemcpyAsync(d_out, x, (size_t)NX * 4, cudaMemcpyDeviceToDevice);
}

// round 6
// speedup vs baseline: 4.2174x; 1.1592x over previous
#include <cuda_runtime.h>
#include <cuda_bf16.h>
#include <math.h>
#include <stdint.h>

typedef __nv_bfloat16 bf16;

// ---------------- problem dims ----------------
#define LY 4
#define BN 4
#define T_ 1024
#define TC 1024
#define T1 2048
#define D_ 384
#define DK 256
#define FF 1536
#define TTMIX 0.1f
#define LN_EPS 1e-5f

#define NX   (BN*T_*D_)
#define NAT  (BN*T_*T1)
#define NQX  (BN*T_*DK)
#define NH_  (BN*T_*FF)
#define NMEM (BN*T1*DK)
#define NOC  (LY*BN*TC*D_)
#define NSCT (BN*T1*TC)
#define NM2  (BN*T1*D_)
#define NWQT (LY*D_*D_)
#define NWKT (LY*D_*DK)
#define NW1  (LY*FF*D_)

// ---------------- scratch ----------------
__device__ __align__(128) float g_x[NX], g_att[NAT], g_mix[NAT];
__device__ __align__(128) float g_m2slab[2*NM2], g_z1slab[4*NQX];
__device__ __align__(128) float g_y2slab[3*NX], g_zslab[2*NX];
__device__ __align__(128) float g_pvec[DK], g_wvec[LY*BN*T1];
__device__ __align__(128) bf16 g_xh[NX], g_xl[NX], g_qxh[NQX], g_qxl[NQX];
__device__ __align__(128) bf16 g_mh[NMEM], g_ml[NMEM], g_mth[NMEM], g_mtl[NMEM];
__device__ __align__(128) bf16 g_unh[NX], g_unl[NX], g_knh[NX], g_knl[NX];
__device__ __align__(128) bf16 g_m2h[LY*NM2], g_m2l[LY*NM2];
__device__ __align__(128) bf16 g_blh[NAT], g_bll[NAT];
__device__ __align__(128) bf16 g_hh[NH_], g_hl[NH_];
__device__ __align__(128) bf16 g_oh[NOC], g_ol[NOC], g_sth[NSCT], g_stl[NSCT];
__device__ __align__(128) bf16 g_wqth[NWQT], g_wqtl[NWQT];
__device__ __align__(128) bf16 g_wkth[NWKT], g_wktl[NWKT];
__device__ __align__(128) bf16 g_wqkth[NWKT], g_wqktl[NWKT];
__device__ __align__(128) bf16 g_wvh[NWKT], g_wvl[NWKT];
__device__ __align__(128) bf16 g_wnh[NWQT], g_wnl[NWQT];
__device__ __align__(128) bf16 g_wuh[NWQT], g_wul[NWQT];
__device__ __align__(128) bf16 g_w1h[NW1], g_w1l[NW1], g_w2h[NW1], g_w2l[NW1];

// ---------------- helpers ----------------
__device__ __forceinline__ uint32_t u32smem(const void* p) {
    uint32_t a;
    asm("{ .reg .u64 t; cvta.to.shared.u64 t, %1; cvt.u32.u64 %0, t; }" : "=r"(a) : "l"(p));
    return a;
}
__device__ __forceinline__ void cpa16(uint32_t s, const void* g) {
    asm volatile("cp.async.cg.shared.global [%0], [%1], 16;" :: "r"(s), "l"(g));
}
#define CP_COMMIT() asm volatile("cp.async.commit_group;" ::: "memory")
#define CP_WAIT(n)  asm volatile("cp.async.wait_group %0;" :: "n"(n) : "memory")

__device__ __forceinline__ void ldsm_x4(uint32_t& r0, uint32_t& r1, uint32_t& r2,
                                        uint32_t& r3, uint32_t a) {
    asm volatile("ldmatrix.sync.aligned.m8n8.x4.shared.b16 {%0,%1,%2,%3}, [%4];"
                 : "=r"(r0), "=r"(r1), "=r"(r2), "=r"(r3) : "r"(a));
}
__device__ __forceinline__ void mma16816(float* d, const uint32_t* a, const uint32_t* b) {
    asm volatile(
        "mma.sync.aligned.m16n8k16.row.col.f32.bf16.bf16.f32 "
        "{%0,%1,%2,%3},{%4,%5,%6,%7},{%8,%9},{%0,%1,%2,%3};"
        : "+f"(d[0]), "+f"(d[1]), "+f"(d[2]), "+f"(d[3])
        : "r"(a[0]), "r"(a[1]), "r"(a[2]), "r"(a[3]), "r"(b[0]), "r"(b[1]));
}
__device__ __forceinline__ bf16 bhi(float x) { return __float2bfloat16(x); }
__device__ __forceinline__ bf16 blo(float x, bf16 h) { return __float2bfloat16(x - __bfloat162float(h)); }

// ---------------- split-bf16 tensor GEMM ----------------
#define STAGES 3
#define STAGE_BYTES 32768

__global__ void __launch_bounds__(256, 2)
mma_gemm(const bf16* __restrict__ Ah, const bf16* __restrict__ Al,
         const bf16* __restrict__ Bh, const bf16* __restrict__ Bl,
         const float* __restrict__ bias, float alpha, int flags,
         float* __restrict__ Cf, bf16* __restrict__ Ch, bf16* __restrict__ Cl,
         int M, int N, int K, long long sA, long long sB, long long sC,
         int kspl, long long slabStride)
{
    extern __shared__ char sm[];
    const int tid = threadIdx.x, lane = tid & 31, wid = tid >> 5;
    const int wm = wid & 3, wn = wid >> 2;
    const int zb = blockIdx.z;
    const long long bz = zb / kspl;
    const int ks = zb - (int)bz * kspl;
    const int Kc = K / kspl;
    const int bm0 = blockIdx.y << 7, bn0 = blockIdx.x << 7;

    const char* gsrc[4] = {
        (const char*)(Ah + bz * sA + (long long)bm0 * K),
        (const char*)(Al + bz * sA + (long long)bm0 * K),
        (const char*)(Bh + bz * sB + (long long)bn0 * K),
        (const char*)(Bl + bz * sB + (long long)bn0 * K) };
    const uint32_t sbase = u32smem(sm);
    const long long rowbytes = (long long)K * 2;

    float acc[2][8][4];
    #pragma unroll
    for (int i = 0; i < 2; i++)
        #pragma unroll
        for (int j = 0; j < 8; j++)
            #pragma unroll
            for (int q = 0; q < 4; q++) acc[i][j][q] = 0.f;

    const int nc = Kc >> 5;
    const int kbase = ks * Kc;

    auto load_stage = [&](int buf, int k0) {
        uint32_t sb = sbase + buf * STAGE_BYTES;
        #pragma unroll
        for (int t = 0; t < 4; t++) {
            uint32_t ab = sb + t * 8192;
            const char* g = gsrc[t];
            #pragma unroll
            for (int i = 0; i < 2; i++) {
                int idx = i * 256 + tid;
                int r = idx >> 2, c = idx & 3;
                uint32_t so = ab + r * 64 + ((c ^ ((r >> 1) & 3)) << 4);
                cpa16(so, g + (long long)r * rowbytes + (long long)k0 * 2 + c * 16);
            }
        }
    };

    auto compute = [&](int buf) {
        uint32_t sb = sbase + buf * STAGE_BYTES;
        #pragma unroll
        for (int s = 0; s < 2; s++) {
            uint32_t a_h[2][4], a_l[2][4];
            #pragma unroll
            for (int mi = 0; mi < 2; mi++) {
                int row = wm * 32 + mi * 16 + (lane & 15);
                int kc  = 2 * s + (lane >> 4);
                uint32_t off = row * 64 + ((kc ^ ((row >> 1) & 3)) << 4);
                ldsm_x4(a_h[mi][0], a_h[mi][1], a_h[mi][2], a_h[mi][3], sb + off);
                ldsm_x4(a_l[mi][0], a_l[mi][1], a_l[mi][2], a_l[mi][3], sb + 8192 + off);
            }
            #pragma unroll
            for (int nj = 0; nj < 4; nj++) {
                int row = wn * 64 + nj * 16 + (lane & 15);
                int kc  = 2 * s + (lane >> 4);
                uint32_t off = row * 64 + ((kc ^ ((row >> 1) & 3)) << 4);
                uint32_t h0, h1, h2, h3, l0, l1, l2, l3;
                ldsm_x4(h0, h1, h2, h3, sb + 16384 + off);
                ldsm_x4(l0, l1, l2, l3, sb + 24576 + off);
                uint32_t bh0[2] = {h0, h2}, bh1[2] = {h1, h3};
                uint32_t bl0[2] = {l0, l2}, bl1[2] = {l1, l3};
                #pragma unroll
                for (int mi = 0; mi < 2; mi++) {
                    mma16816(acc[mi][2*nj],   a_h[mi], bh0);
                    mma16816(acc[mi][2*nj],   a_h[mi], bl0);
                    mma16816(acc[mi][2*nj],   a_l[mi], bh0);
                    mma16816(acc[mi][2*nj+1], a_h[mi], bh1);
                    mma16816(acc[mi][2*nj+1], a_h[mi], bl1);
                    mma16816(acc[mi][2*nj+1], a_l[mi], bh1);
                }
            }
        }
    };

    #pragma unroll
    for (int s = 0; s < STAGES - 1; s++) {
        if (s < nc) load_stage(s, kbase + s * 32);
        CP_COMMIT();
    }
    int buf = 0, nxt = STAGES - 1;
    for (int c = 0; c < nc; c++) {
        CP_WAIT(STAGES - 2);
        __syncthreads();
        if (c + STAGES - 1 < nc) {
            load_stage(nxt, kbase + (c + STAGES - 1) * 32);
            CP_COMMIT();
        } else {
            CP_COMMIT();
        }
        compute(buf);
        if (++buf == STAGES) buf = 0;
        if (++nxt == STAGES) nxt = 0;
    }

    float* Cfo = Cf ? Cf + (long long)ks * slabStride : nullptr;
    const int rl = lane >> 2, cl = (lane & 3) * 2;
    #pragma unroll
    for (int mi = 0; mi < 2; mi++) {
        #pragma unroll
        for (int hf = 0; hf < 2; hf++) {
            const long long grow = bm0 + wm * 32 + mi * 16 + rl + hf * 8;
            float brow = 0.f;
            if (bias && (flags & 2)) brow = bias[grow];
            const long long base = bz * sC + grow * (long long)N + bn0 + wn * 64;
            #pragma unroll
            for (int nb = 0; nb < 8; nb++) {
                const int coff = nb * 8 + cl;
                float v0 = acc[mi][nb][hf*2+0] * alpha;
                float v1 = acc[mi][nb][hf*2+1] * alpha;
                if (bias) {
                    if (flags & 2) { v0 += brow; v1 += brow; }
                    else {
                        const long long gcol = bn0 + wn * 64 + coff;
                        v0 += bias[gcol]; v1 += bias[gcol + 1];
                    }
                }
                if (flags & 1) { v0 = fmaxf(v0, 0.f); v1 = fmaxf(v1, 0.f); }
                if (Cfo) *reinterpret_cast<float2*>(Cfo + base + coff) = make_float2(v0, v1);
                if (Ch) {
                    bf16 h0 = bhi(v0), h1 = bhi(v1);
                    __nv_bfloat162 hh = __halves2bfloat162(h0, h1);
                    __nv_bfloat162 ll = __halves2bfloat162(blo(v0, h0), blo(v1, h1));
                    *reinterpret_cast<uint32_t*>(Ch + base + coff) = *reinterpret_cast<uint32_t*>(&hh);
                    *reinterpret_cast<uint32_t*>(Cl + base + coff) = *reinterpret_cast<uint32_t*>(&ll);
                }
            }
        }
    }
}

// ---------------- fp32 -> (hi,lo) bf16 split ----------------
__global__ void cvt_split(const float* __restrict__ in, bf16* __restrict__ hi,
                          bf16* __restrict__ lo, long long n4)
{
    long long i = blockIdx.x * (long long)blockDim.x + threadIdx.x;
    if (i >= n4) return;
    float4 v = reinterpret_cast<const float4*>(in)[i];
    bf16 h0 = bhi(v.x), h1 = bhi(v.y), h2 = bhi(v.z), h3 = bhi(v.w);
    __nv_bfloat162 a = __halves2bfloat162(h0, h1), b = __halves2bfloat162(h2, h3);
    __nv_bfloat162 c = __halves2bfloat162(blo(v.x, h0), blo(v.y, h1));
    __nv_bfloat162 d = __halves2bfloat162(blo(v.z, h2), blo(v.w, h3));
    reinterpret_cast<uint2*>(hi)[i] = make_uint2(*(uint32_t*)&a, *(uint32_t*)&b);
    reinterpret_cast<uint2*>(lo)[i] = make_uint2(*(uint32_t*)&c, *(uint32_t*)&d);
}

// ---------------- sum ns slabs (fp32) -> hi/lo bf16 ----------------
__global__ void reduce_split(const float* __restrict__ slabs, long long sstride4,
                             int ns, bf16* __restrict__ hi, bf16* __restrict__ lo,
                             long long n4)
{
    long long i = blockIdx.x * (long long)blockDim.x + threadIdx.x;
    if (i >= n4) return;
    const float4* p = reinterpret_cast<const float4*>(slabs);
    float4 v = p[i];
    for (int s = 1; s < ns; s++) {
        float4 t = p[i + s * sstride4];
        v.x += t.x; v.y += t.y; v.z += t.z; v.w += t.w;
    }
    bf16 h0 = bhi(v.x), h1 = bhi(v.y), h2 = bhi(v.z), h3 = bhi(v.w);
    __nv_bfloat162 a = __halves2bfloat162(h0, h1), b = __halves2bfloat162(h2, h3);
    __nv_bfloat162 c = __halves2bfloat162(blo(v.x, h0), blo(v.y, h1));
    __nv_bfloat162 d = __halves2bfloat162(blo(v.z, h2), blo(v.w, h3));
    reinterpret_cast<uint2*>(hi)[i] = make_uint2(*(uint32_t*)&a, *(uint32_t*)&b);
    reinterpret_cast<uint2*>(lo)[i] = make_uint2(*(uint32_t*)&c, *(uint32_t*)&d);
}

// ---------------- transpose+split: [batch,R,C] f32 -> [batch,C,R] hi/lo ------
__global__ void transpose_split_g(const float* __restrict__ in,
                                  bf16* __restrict__ oh, bf16* __restrict__ ol,
                                  int R, int C)
{
    __shared__ float tile[32][33];
    const long long b = blockIdx.z;
    const int c0 = blockIdx.x << 5;
    const int r0 = blockIdx.y << 5;
    const float* ib = in + b * (long long)R * C;
    const int tx = threadIdx.x, ty = threadIdx.y;
    #pragma unroll
    for (int i = 0; i < 4; i++)
        tile[ty + 8*i][tx] = ib[(long long)(r0 + ty + 8*i) * C + c0 + tx];
    __syncthreads();
    bf16* ohb = oh + b * (long long)R * C;
    bf16* olb = ol + b * (long long)R * C;
    #pragma unroll
    for (int i = 0; i < 4; i++) {
        float v = tile[tx][ty + 8*i];
        bf16 h = bhi(v);
        long long o = (long long)(c0 + ty + 8*i) * R + r0 + tx;
        ohb[o] = h;
        olb[o] = blo(v, h);
    }
}

// ---------------- bias-fold vectors ----------------
__global__ void pvec_k(const float* __restrict__ Wk, const float* __restrict__ bq,
                       float* __restrict__ pvec)
{
    int dk = threadIdx.x;
    float s = 0.f;
    for (int e = 0; e < D_; e++) s += bq[e] * Wk[(long long)e * DK + dk];
    pvec[dk] = s;
}
__global__ void wvec_k(const float* __restrict__ mem, const float* __restrict__ pvec,
                       float* __restrict__ w, float scale)
{
    int i = blockIdx.x * 256 + threadIdx.x;
    const float* m = mem + (long long)i * DK;
    float s = 0.f;
    #pragma unroll 8
    for (int dk = 0; dk < DK; dk++) s += m[dk] * pvec[dk];
    w[i] = s * scale;
}

// ---------------- reductions ----------------
__device__ __forceinline__ float warpMax(float v) {
    #pragma unroll
    for (int o = 16; o > 0; o >>= 1) v = fmaxf(v, __shfl_xor_sync(0xffffffffu, v, o));
    return v;
}
__device__ __forceinline__ float warpSum(float v) {
    #pragma unroll
    for (int o = 16; o > 0; o >>= 1) v += __shfl_xor_sync(0xffffffffu, v, o);
    return v;
}
__device__ __forceinline__ float blockMax(float v) {
    __shared__ float sh[8];
    v = warpMax(v);
    __syncthreads();
    if ((threadIdx.x & 31) == 0) sh[threadIdx.x >> 5] = v;
    __syncthreads();
    float r = -1e30f;
    int nw = blockDim.x >> 5;
    #pragma unroll
    for (int i = 0; i < 8; i++) if (i < nw) r = fmaxf(r, sh[i]);
    return r;
}
__device__ __forceinline__ float blockSum(float v) {
    __shared__ float sh[8];
    v = warpSum(v);
    __syncthreads();
    if ((threadIdx.x & 31) == 0) sh[threadIdx.x >> 5] = v;
    __syncthreads();
    float r = 0.0f;
    int nw = blockDim.x >> 5;
    #pragma unroll
    for (int i = 0; i < 8; i++) if (i < nw) r += sh[i];
    return r;
}

// ---------------- dual softmax + blend ----------------
__global__ void __launch_bounds__(256)
softmax_blend(const float* __restrict__ mixed, const float* __restrict__ att,
              const float* __restrict__ w,
              bf16* __restrict__ oh, bf16* __restrict__ ol)
{
    const long long base = (long long)blockIdx.x * T1;
    const int b = blockIdx.x >> 10;
    const int tid = threadIdx.x;
    float mv[8], av[8];
    float m1 = -1e30f, m2 = -1e30f;
    #pragma unroll
    for (int i = 0; i < 8; i++) {
        int c = tid + i * 256;
        mv[i] = mixed[base + c];
        av[i] = att[base + c] + w[(long long)b * T1 + c];
        m1 = fmaxf(m1, mv[i]);
        m2 = fmaxf(m2, av[i]);
    }
    m1 = blockMax(m1);
    m2 = blockMax(m2);
    float s1 = 0.f, s2 = 0.f;
    #pragma unroll
    for (int i = 0; i < 8; i++) {
        mv[i] = __expf(mv[i] - m1);
        av[i] = __expf(av[i] - m2);
        s1 += mv[i]; s2 += av[i];
    }
    s1 = blockSum(s1);
    s2 = blockSum(s2);
    const float r1 = TTMIX / s1, r2 = (1.0f - TTMIX) / s2;
    #pragma unroll
    for (int i = 0; i < 8; i++) {
        int c = tid + i * 256;
        float v = mv[i] * r1 + av[i] * r2;
        bf16 h = bhi(v);
        oh[base + c] = h;
        ol[base + c] = blo(v, h);
    }
}

// ---------------- residual add + LayerNorm ----------------
__global__ void __launch_bounds__(128)
add_ln(float* __restrict__ x, const float* __restrict__ slabs, int ns,
       long long sstride, const float* __restrict__ bias2,
       const float* __restrict__ g, const float* __restrict__ b,
       bf16* __restrict__ xh, bf16* __restrict__ xl)
{
    const long long base = (long long)blockIdx.x * D_;
    const int tid = threadIdx.x;
    float v[3];
    #pragma unroll
    for (int i = 0; i < 3; i++) {
        int c = tid + i * 128;
        float t = x[base + c];
        for (int s = 0; s < ns; s++) t += slabs[s * sstride + base + c];
        if (bias2) t += bias2[c];
        v[i] = t;
    }
    float s = v[0] + v[1] + v[2];
    s = blockSum(s);
    const float mean = s * (1.0f / D_);
    float q = 0.f;
    #pragma unroll
    for (int i = 0; i < 3; i++) { float d = v[i] - mean; q += d * d; }
    q = blockSum(q);
    const float rstd = rsqrtf(q * (1.0f / D_) + LN_EPS);
    #pragma unroll
    for (int i = 0; i < 3; i++) {
        int c = tid + i * 128;
        float o = (v[i] - mean) * rstd * g[c] + b[c];
        x[base + c] = o;
        bf16 h = bhi(o);
        xh[base + c] = h;
        xl[base + c] = blo(o, h);
    }
}

// ---------------- host ----------------
#define SMEM_DYN (STAGES * STAGE_BYTES)
#define SYM(p, s) do { void* _t; cudaGetSymbolAddress(&_t, s); p = (decltype(p))_t; } while (0)

static void split(const float* in, bf16* hi, bf16* lo, long long n, cudaStream_t st) {
    long long n4 = n / 4;
    cvt_split<<<(unsigned)((n4 + 255) / 256), 256, 0, st>>>(in, hi, lo, n4);
}
static void gemm(const bf16* Ah, const bf16* Al, const bf16* Bh, const bf16* Bl,
                 const float* bias, float alpha, int flags,
                 float* Cf, bf16* Ch, bf16* Cl,
                 int M, int N, int K, int batch,
                 long long sA, long long sB, long long sC, cudaStream_t st,
                 int kspl = 1, long long slabStride = 0) {
    dim3 g(N / 128, M / 128, batch * kspl);
    mma_gemm<<<g, 256, SMEM_DYN, st>>>(Ah, Al, Bh, Bl, bias, alpha, flags,
                                       Cf, Ch, Cl, M, N, K, sA, sB, sC,
                                       kspl, slabStride);
}
static void transpose_split(const float* in, bf16* oh, bf16* ol,
                            int R, int C, int batch, cudaStream_t st) {
    dim3 g(C / 32, R / 32, batch), b(32, 8);
    transpose_split_g<<<g, b, 0, st>>>(in, oh, ol, R, C);
}

extern "C" void kernel_launch(void* const* d_in, const int* in_sizes, int n_in,
                              void* d_out, int out_size)
{
    (void)in_sizes; (void)n_in; (void)out_size;
    const float* tgt     = (const float*)d_in[0];
    const float* memory  = (const float*)d_in[1];
    const float* score_c = (const float*)d_in[2];
    const float* out_c   = (const float*)d_in[3];
    const float* Wq  = (const float*)d_in[4];
    const float* bq  = (const float*)d_in[5];
    const float* Wk  = (const float*)d_in[6];
    const float* Wv  = (const float*)d_in[8];
    const float* bv  = (const float*)d_in[9];
    const float* Wkn = (const float*)d_in[10];
    const float* bkn = (const float*)d_in[11];
    const float* Wun = (const float*)d_in[12];
    const float* bun = (const float*)d_in[13];
    const float* W1  = (const float*)d_in[14];
    const float* b1  = (const float*)d_in[15];
    const float* W2  = (const float*)d_in[16];
    const float* b2  = (const float*)d_in[17];
    const float* g1  = (const float*)d_in[18];
    const float* be1 = (const float*)d_in[19];
    const float* g2  = (const float*)d_in[20];
    const float* be2 = (const float*)d_in[21];

    float *x, *att, *mix, *m2slab, *z1slab, *y2slab, *zslab, *pvec, *wvec;
    SYM(x, g_x); SYM(att, g_att); SYM(mix, g_mix);
    SYM(m2slab, g_m2slab); SYM(z1slab, g_z1slab);
    SYM(y2slab, g_y2slab); SYM(zslab, g_zslab);
    SYM(pvec, g_pvec); SYM(wvec, g_wvec);
    bf16 *xh,*xl,*qxh,*qxl,*mh,*ml,*mth,*mtl,*unh,*unl,*knh,*knl,*m2h,*m2l,*blh,*bll,*hh,*hl;
    bf16 *oh,*ol,*sth,*stl;
    bf16 *wqth,*wqtl,*wkth,*wktl,*wqkth,*wqktl,*wvh,*wvl,*wnh,*wnl,*wuh,*wul,*w1h,*w1l,*w2h,*w2l;
    SYM(xh,g_xh); SYM(xl,g_xl); SYM(qxh,g_qxh); SYM(qxl,g_qxl);
    SYM(mh,g_mh); SYM(ml,g_ml); SYM(mth,g_mth); SYM(mtl,g_mtl);
    SYM(unh,g_unh); SYM(unl,g_unl); SYM(knh,g_knh); SYM(knl,g_knl);
    SYM(m2h,g_m2h); SYM(m2l,g_m2l); SYM(blh,g_blh); SYM(bll,g_bll);
    SYM(hh,g_hh); SYM(hl,g_hl); SYM(oh,g_oh); SYM(ol,g_ol);
    SYM(sth,g_sth); SYM(stl,g_stl);
    SYM(wqth,g_wqth); SYM(wqtl,g_wqtl); SYM(wkth,g_wkth); SYM(wktl,g_wktl);
    SYM(wqkth,g_wqkth); SYM(wqktl,g_wqktl);
    SYM(wvh,g_wvh); SYM(wvl,g_wvl); SYM(wnh,g_wnh); SYM(wnl,g_wnl);
    SYM(wuh,g_wuh); SYM(wul,g_wul);
    SYM(w1h,g_w1h); SYM(w1l,g_w1l); SYM(w2h,g_w2h); SYM(w2l,g_w2l);

    cudaFuncSetAttribute(mma_gemm, cudaFuncAttributeMaxDynamicSharedMemorySize, SMEM_DYN);

    // ---- streams/events (created once; host-side only, identical captured work)
    static cudaStream_t s1 = nullptr, s2 = nullptr;
    static cudaEvent_t e0 = nullptr, s1done = nullptr;
    static cudaEvent_t ev_m2t[LY], ev_att[LY], ev_x[LY];
    if (!s1) {
        cudaStreamCreateWithFlags(&s1, cudaStreamNonBlocking);
        cudaStreamCreateWithFlags(&s2, cudaStreamNonBlocking);
        cudaEventCreateWithFlags(&e0, cudaEventDisableTiming);
        cudaEventCreateWithFlags(&s1done, cudaEventDisableTiming);
        for (int l = 0; l < LY; l++) {
            cudaEventCreateWithFlags(&ev_m2t[l], cudaEventDisableTiming);
            cudaEventCreateWithFlags(&ev_att[l], cudaEventDisableTiming);
            cudaEventCreateWithFlags(&ev_x[l], cudaEventDisableTiming);
        }
    }

    const float scale = 1.0f / sqrtf((float)D_);
    cudaStream_t s0 = 0;

    // ---- prologue (main stream) ----
    cudaMemcpyAsync(x, tgt, (size_t)NX * 4, cudaMemcpyDeviceToDevice, s0);
    split(tgt, xh, xl, NX, s0);
    split(memory, mh, ml, NMEM, s0);
    split(out_c, oh, ol, NOC, s0);
    split(Wv, wvh, wvl, NWKT, s0);
    split(Wkn, wnh, wnl, NWQT, s0);
    split(Wun, wuh, wul, NWQT, s0);
    split(W1, w1h, w1l, NW1, s0);
    split(W2, w2h, w2l, NW1, s0);
    transpose_split(memory, mth, mtl, T1, DK, BN, s0);
    transpose_split(Wq, wqth, wqtl, D_, D_, LY, s0);
    transpose_split(Wk, wkth, wktl, D_, DK, LY, s0);
    gemm(wkth, wktl, wqth, wqtl, nullptr, 1.f, 0, nullptr, wqkth, wqktl,
         DK, D_, D_, LY, (long long)DK*D_, (long long)D_*D_, (long long)DK*D_, s0);
    for (int l = 0; l < LY; l++) {
        pvec_k<<<1, DK, 0, s0>>>(Wk + (long long)l*D_*DK, bq + (long long)l*D_, pvec);
        wvec_k<<<BN*T1/256, 256, 0, s0>>>(memory, pvec, wvec + (long long)l*BN*T1, scale);
    }
    cudaEventRecord(e0, s0);

    // ---- stream s1: x-independent precompute (all layers) ----
    cudaStreamWaitEvent(s1, e0, 0);
    for (int l = 0; l < LY; l++) {
        const long long oq = (long long)l * D_ * D_;
        // knoT_b = Wkn @ out_c_b^T + bkn (row bias): [D, TC]
        gemm(wnh + oq, wnl + oq,
             oh + (long long)l*BN*TC*D_, ol + (long long)l*BN*TC*D_,
             bkn + (long long)l*D_, 1.f, 2, nullptr, knh, knl,
             D_, TC, D_, BN, 0, (long long)TC*D_, (long long)D_*TC, s1);
        // score_c[l]^T -> sth [B, T1, TC]
        transpose_split(score_c + (long long)l*BN*TC*T1, sth, stl, TC, T1, BN, s1);
        // M2T_b = scale * sth_b @ knoT_b^T : [T1, D], split-K=2
        gemm(sth, stl, knh, knl, nullptr, scale, 0, m2slab, nullptr, nullptr,
             T1, D_, TC, BN, (long long)T1*TC, (long long)D_*TC, (long long)T1*D_,
             s1, 2, (long long)NM2);
        reduce_split<<<(NM2/4 + 255)/256, 256, 0, s1>>>(
            m2slab, NM2/4, 2, m2h + (long long)l*NM2, m2l + (long long)l*NM2, NM2/4);
        cudaEventRecord(ev_m2t[l], s1);
    }
    cudaEventRecord(s1done, s1);

    // ---- main + s2 per-layer ----
    for (int l = 0; l < LY; l++) {
        const long long oq = (long long)l * D_ * D_;
        const long long ok = (long long)l * D_ * DK;
        const long long o1 = (long long)l * FF * D_;

        // s2: qx -> att (depends on current x)
        cudaStreamWaitEvent(s2, (l == 0) ? e0 : ev_x[l], 0);
        gemm(xh, xl, wqkth + ok, wqktl + ok, nullptr, 1.f, 0, nullptr, qxh, qxl,
             BN*T_, DK, D_, 1, 0, 0, 0, s2);
        gemm(qxh, qxl, mh, ml, nullptr, scale, 0, att, nullptr, nullptr,
             T_, T1, DK, BN, (long long)T_*DK, (long long)T1*DK, (long long)T_*T1, s2);
        cudaEventRecord(ev_att[l], s2);

        // main: unk
        gemm(xh, xl, wuh + oq, wul + oq, bun + (long long)l*D_, 1.f, 0,
             nullptr, unh, unl, BN*T_, D_, D_, 1, 0, 0, 0, s0);
        // main: mixed (needs M2T[l])
        cudaStreamWaitEvent(s0, ev_m2t[l], 0);
        gemm(unh, unl, m2h + (long long)l*NM2, m2l + (long long)l*NM2,
             nullptr, 1.f, 0, mix, nullptr, nullptr,
             T_, T1, D_, BN, (long long)T_*D_, (long long)T1*D_, (long long)T_*T1, s0);
        // main: softmax blend (needs att)
        cudaStreamWaitEvent(s0, ev_att[l], 0);
        softmax_blend<<<BN*T_, 256, 0, s0>>>(mix, att, wvec + (long long)l*BN*T1, blh, bll);
        // z1 = blended @ memT^T, split-K=4
        gemm(blh, bll, mth, mtl, nullptr, 1.f, 0, z1slab, nullptr, nullptr,
             T_, DK, T1, BN, (long long)T_*T1, (long long)DK*T1, (long long)T_*DK,
             s0, 4, (long long)NQX);
        reduce_split<<<(NQX/4 + 255)/256, 256, 0, s0>>>(z1slab, NQX/4, 4, qxh, qxl, NQX/4);
        // z = z1 @ Wv^T, split-K=2 (bv added in add_ln)
        gemm(qxh, qxl, wvh + ok, wvl + ok, nullptr, 1.f, 0,
             zslab, nullptr, nullptr, BN*T_, D_, DK, 1, 0, 0, 0, s0, 2, (long long)NX);
        add_ln<<<BN*T_, 128, 0, s0>>>(x, zslab, 2, (long long)NX, bv + (long long)l*D_,
                                      g1 + (long long)l*D_, be1 + (long long)l*D_, xh, xl);
        // h = relu(x @ W1^T + b1)
        gemm(xh, xl, w1h + o1, w1l + o1, b1 + (long long)l*FF, 1.f, 1,
             nullptr, hh, hl, BN*T_, FF, D_, 1, 0, 0, 0, s0);
        // y2 = h @ W2^T, split-K=3 (b2 added in add_ln)
        gemm(hh, hl, w2h + o1, w2l + o1, nullptr, 1.f, 0, y2slab, nullptr, nullptr,
             BN*T_, D_, FF, 1, 0, 0, 0, s0, 3, (long long)NX);
        add_ln<<<BN*T_, 128, 0, s0>>>(x, y2slab, 3, (long long)NX, b2 + (long long)l*D_,
                                      g2 + (long long)l*D_, be2 + (long long)l*D_, xh, xl);
        if (l + 1 < LY) cudaEventRecord(ev_x[l + 1], s0);
    }

    // join s1 (in case main never waited on its last event being the join point)
    cudaStreamWaitEvent(s0, s1done, 0);
    cudaMemcpyAsync(d_out, x, (size_t)NX * 4, cudaMemcpyDeviceToDevice, s0);
}

// round 7
// speedup vs baseline: 7.7241x; 1.8315x over previous
#include <cuda_runtime.h>
#include <cuda_fp16.h>
#include <math.h>
#include <stdint.h>

typedef __half h16;

// ---------------- problem dims ----------------
#define LY 4
#define BN 4
#define T_ 1024
#define TC 1024
#define T1 2048
#define D_ 384
#define DK 256
#define FF 1536
#define TTMIX 0.1f
#define LN_EPS 1e-5f

#define NX   (BN*T_*D_)
#define NAT  (BN*T_*T1)
#define NQX  (BN*T_*DK)
#define NH_  (BN*T_*FF)
#define NMEM (BN*T1*DK)
#define NOC  (LY*BN*TC*D_)
#define NSCT (BN*T1*TC)
#define NM2  (BN*T1*D_)
#define NWQT (LY*D_*D_)
#define NWKT (LY*D_*DK)
#define NW1  (LY*FF*D_)

// ---------------- scratch ----------------
__device__ __align__(128) float g_x[NX], g_att[NAT], g_mix[NAT];
__device__ __align__(128) float g_m2slab[2*NM2], g_z1slab[4*NQX];
__device__ __align__(128) float g_y2slab[3*NX], g_zslab[2*NX];
__device__ __align__(128) float g_pvec[DK], g_wvec[LY*BN*T1];
__device__ __align__(128) h16 g_xh[NX], g_qxh[NQX];
__device__ __align__(128) h16 g_mh[NMEM], g_mth[NMEM];
__device__ __align__(128) h16 g_unh[NX], g_knh[NX];
__device__ __align__(128) h16 g_m2h[LY*NM2];
__device__ __align__(128) h16 g_blh[NAT];
__device__ __align__(128) h16 g_hh[NH_];
__device__ __align__(128) h16 g_oh[NOC], g_sth[NSCT];
__device__ __align__(128) h16 g_wqth[NWQT], g_wkth[NWKT], g_wqkth[NWKT];
__device__ __align__(128) h16 g_wvh[NWKT], g_wnh[NWQT], g_wuh[NWQT];
__device__ __align__(128) h16 g_w1h[NW1], g_w2h[NW1];

// ---------------- helpers ----------------
__device__ __forceinline__ uint32_t u32smem(const void* p) {
    uint32_t a;
    asm("{ .reg .u64 t; cvta.to.shared.u64 t, %1; cvt.u32.u64 %0, t; }" : "=r"(a) : "l"(p));
    return a;
}
__device__ __forceinline__ void cpa16(uint32_t s, const void* g) {
    asm volatile("cp.async.cg.shared.global [%0], [%1], 16;" :: "r"(s), "l"(g));
}
#define CP_COMMIT() asm volatile("cp.async.commit_group;" ::: "memory")
#define CP_WAIT(n)  asm volatile("cp.async.wait_group %0;" :: "n"(n) : "memory")

__device__ __forceinline__ void ldsm_x4(uint32_t& r0, uint32_t& r1, uint32_t& r2,
                                        uint32_t& r3, uint32_t a) {
    asm volatile("ldmatrix.sync.aligned.m8n8.x4.shared.b16 {%0,%1,%2,%3}, [%4];"
                 : "=r"(r0), "=r"(r1), "=r"(r2), "=r"(r3) : "r"(a));
}
__device__ __forceinline__ void mma16816(float* d, const uint32_t* a, const uint32_t* b) {
    asm volatile(
        "mma.sync.aligned.m16n8k16.row.col.f32.f16.f16.f32 "
        "{%0,%1,%2,%3},{%4,%5,%6,%7},{%8,%9},{%0,%1,%2,%3};"
        : "+f"(d[0]), "+f"(d[1]), "+f"(d[2]), "+f"(d[3])
        : "r"(a[0]), "r"(a[1]), "r"(a[2]), "r"(a[3]), "r"(b[0]), "r"(b[1]));
}

// ---------------- fp16 tensor GEMM: C = alpha*A@B^T (+bias)(+relu) -----------
// A:[M,K] fp16, B:[N,K] fp16 (K-major). CTA 128x128, BK=64, 3-stage cp.async,
// 2 CTAs/SM. flags: 1=relu, 2=bias by row (else col). Split-K via kspl.
#define STAGES 3
#define STAGE_BYTES 32768   // A 16KB + B 16KB

__global__ void __launch_bounds__(256, 2)
mma_gemm(const h16* __restrict__ A, const h16* __restrict__ B,
         const float* __restrict__ bias, float alpha, int flags,
         float* __restrict__ Cf, h16* __restrict__ Ch,
         int M, int N, int K, long long sA, long long sB, long long sC,
         int kspl, long long slabStride)
{
    extern __shared__ char sm[];
    const int tid = threadIdx.x, lane = tid & 31, wid = tid >> 5;
    const int wm = wid & 3, wn = wid >> 2;          // warp tile 32(m) x 64(n)
    const int zb = blockIdx.z;
    const long long bz = zb / kspl;
    const int ks = zb - (int)bz * kspl;
    const int Kc = K / kspl;
    const int bm0 = blockIdx.y << 7, bn0 = blockIdx.x << 7;

    const char* gsrc[2] = {
        (const char*)(A + bz * sA + (long long)bm0 * K),
        (const char*)(B + bz * sB + (long long)bn0 * K) };
    const uint32_t sbase = u32smem(sm);
    const long long rowbytes = (long long)K * 2;

    float acc[2][8][4];
    #pragma unroll
    for (int i = 0; i < 2; i++)
        #pragma unroll
        for (int j = 0; j < 8; j++)
            #pragma unroll
            for (int q = 0; q < 4; q++) acc[i][j][q] = 0.f;

    const int nc = Kc >> 6;
    const int kbase = ks * Kc;

    auto load_stage = [&](int buf, int k0) {
        uint32_t sb = sbase + buf * STAGE_BYTES;
        #pragma unroll
        for (int t = 0; t < 2; t++) {
            uint32_t ab = sb + t * 16384;
            const char* g = gsrc[t];
            #pragma unroll
            for (int i = 0; i < 4; i++) {
                int idx = i * 256 + tid;
                int r = idx >> 3, c = idx & 7;
                uint32_t so = ab + r * 128 + ((c ^ (r & 7)) << 4);
                cpa16(so, g + (long long)r * rowbytes + (long long)k0 * 2 + c * 16);
            }
        }
    };

    auto compute = [&](int buf) {
        uint32_t sbA = sbase + buf * STAGE_BYTES;
        uint32_t sbB = sbA + 16384;
        #pragma unroll
        for (int s = 0; s < 4; s++) {               // 4 k16 steps in BK=64
            uint32_t a[2][4];
            #pragma unroll
            for (int mi = 0; mi < 2; mi++) {
                int row = wm * 32 + mi * 16 + (lane & 15);
                int c = 2 * s + (lane >> 4);
                uint32_t off = row * 128 + ((c ^ (row & 7)) << 4);
                ldsm_x4(a[mi][0], a[mi][1], a[mi][2], a[mi][3], sbA + off);
            }
            #pragma unroll
            for (int nj = 0; nj < 4; nj++) {
                int row = wn * 64 + nj * 16 + (lane & 15);
                int c = 2 * s + (lane >> 4);
                uint32_t off = row * 128 + ((c ^ (row & 7)) << 4);
                uint32_t r0, r1, r2, r3;
                ldsm_x4(r0, r1, r2, r3, sbB + off);
                uint32_t b0[2] = {r0, r2}, b1[2] = {r1, r3};
                #pragma unroll
                for (int mi = 0; mi < 2; mi++) {
                    mma16816(acc[mi][2*nj],   a[mi], b0);
                    mma16816(acc[mi][2*nj+1], a[mi], b1);
                }
            }
        }
    };

    #pragma unroll
    for (int s = 0; s < STAGES - 1; s++) {
        if (s < nc) load_stage(s, kbase + s * 64);
        CP_COMMIT();
    }
    int buf = 0, nxt = STAGES - 1;
    for (int c = 0; c < nc; c++) {
        CP_WAIT(STAGES - 2);
        __syncthreads();
        if (c + STAGES - 1 < nc) {
            load_stage(nxt, kbase + (c + STAGES - 1) * 64);
            CP_COMMIT();
        } else {
            CP_COMMIT();
        }
        compute(buf);
        if (++buf == STAGES) buf = 0;
        if (++nxt == STAGES) nxt = 0;
    }

    float* Cfo = Cf ? Cf + (long long)ks * slabStride : nullptr;
    const int rl = lane >> 2, cl = (lane & 3) * 2;
    #pragma unroll
    for (int mi = 0; mi < 2; mi++) {
        #pragma unroll
        for (int hf = 0; hf < 2; hf++) {
            const long long grow = bm0 + wm * 32 + mi * 16 + rl + hf * 8;
            float brow = 0.f;
            if (bias && (flags & 2)) brow = bias[grow];
            const long long base = bz * sC + grow * (long long)N + bn0 + wn * 64;
            #pragma unroll
            for (int nb = 0; nb < 8; nb++) {
                const int coff = nb * 8 + cl;
                float v0 = acc[mi][nb][hf*2+0] * alpha;
                float v1 = acc[mi][nb][hf*2+1] * alpha;
                if (bias) {
                    if (flags & 2) { v0 += brow; v1 += brow; }
                    else {
                        const long long gcol = bn0 + wn * 64 + coff;
                        v0 += bias[gcol]; v1 += bias[gcol + 1];
                    }
                }
                if (flags & 1) { v0 = fmaxf(v0, 0.f); v1 = fmaxf(v1, 0.f); }
                if (Cfo) *reinterpret_cast<float2*>(Cfo + base + coff) = make_float2(v0, v1);
                if (Ch) {
                    __half2 p = __floats2half2_rn(v0, v1);
                    *reinterpret_cast<uint32_t*>(Ch + base + coff) =
                        *reinterpret_cast<uint32_t*>(&p);
                }
            }
        }
    }
}

// ---------------- fp32 -> fp16 ----------------
__global__ void cvt16(const float* __restrict__ in, h16* __restrict__ out, long long n4)
{
    long long i = blockIdx.x * (long long)blockDim.x + threadIdx.x;
    if (i >= n4) return;
    float4 v = reinterpret_cast<const float4*>(in)[i];
    __half2 a = __floats2half2_rn(v.x, v.y);
    __half2 b = __floats2half2_rn(v.z, v.w);
    reinterpret_cast<uint2*>(out)[i] = make_uint2(*(uint32_t*)&a, *(uint32_t*)&b);
}

// ---------------- sum ns fp32 slabs -> fp16 ----------------
__global__ void reduce16(const float* __restrict__ slabs, long long sstride4,
                         int ns, h16* __restrict__ out, long long n4)
{
    long long i = blockIdx.x * (long long)blockDim.x + threadIdx.x;
    if (i >= n4) return;
    const float4* p = reinterpret_cast<const float4*>(slabs);
    float4 v = p[i];
    for (int s = 1; s < ns; s++) {
        float4 t = p[i + s * sstride4];
        v.x += t.x; v.y += t.y; v.z += t.z; v.w += t.w;
    }
    __half2 a = __floats2half2_rn(v.x, v.y);
    __half2 b = __floats2half2_rn(v.z, v.w);
    reinterpret_cast<uint2*>(out)[i] = make_uint2(*(uint32_t*)&a, *(uint32_t*)&b);
}

// ---------------- transpose: [batch,R,C] f32 -> [batch,C,R] fp16 -------------
__global__ void transpose16(const float* __restrict__ in, h16* __restrict__ out,
                            int R, int C)
{
    __shared__ float tile[32][33];
    const long long b = blockIdx.z;
    const int c0 = blockIdx.x << 5;
    const int r0 = blockIdx.y << 5;
    const float* ib = in + b * (long long)R * C;
    const int tx = threadIdx.x, ty = threadIdx.y;
    #pragma unroll
    for (int i = 0; i < 4; i++)
        tile[ty + 8*i][tx] = ib[(long long)(r0 + ty + 8*i) * C + c0 + tx];
    __syncthreads();
    h16* ob = out + b * (long long)R * C;
    #pragma unroll
    for (int i = 0; i < 4; i++) {
        float v = tile[tx][ty + 8*i];
        ob[(long long)(c0 + ty + 8*i) * R + r0 + tx] = __float2half_rn(v);
    }
}

// ---------------- bias-fold vectors ----------------
__global__ void pvec_k(const float* __restrict__ Wk, const float* __restrict__ bq,
                       float* __restrict__ pvec)
{
    int dk = threadIdx.x;
    float s = 0.f;
    for (int e = 0; e < D_; e++) s += bq[e] * Wk[(long long)e * DK + dk];
    pvec[dk] = s;
}
__global__ void wvec_k(const float* __restrict__ mem, const float* __restrict__ pvec,
                       float* __restrict__ w, float scale)
{
    int i = blockIdx.x * 256 + threadIdx.x;
    const float* m = mem + (long long)i * DK;
    float s = 0.f;
    #pragma unroll 8
    for (int dk = 0; dk < DK; dk++) s += m[dk] * pvec[dk];
    w[i] = s * scale;
}

// ---------------- reductions ----------------
__device__ __forceinline__ float warpMax(float v) {
    #pragma unroll
    for (int o = 16; o > 0; o >>= 1) v = fmaxf(v, __shfl_xor_sync(0xffffffffu, v, o));
    return v;
}
__device__ __forceinline__ float warpSum(float v) {
    #pragma unroll
    for (int o = 16; o > 0; o >>= 1) v += __shfl_xor_sync(0xffffffffu, v, o);
    return v;
}
__device__ __forceinline__ float blockMax(float v) {
    __shared__ float sh[8];
    v = warpMax(v);
    __syncthreads();
    if ((threadIdx.x & 31) == 0) sh[threadIdx.x >> 5] = v;
    __syncthreads();
    float r = -1e30f;
    int nw = blockDim.x >> 5;
    #pragma unroll
    for (int i = 0; i < 8; i++) if (i < nw) r = fmaxf(r, sh[i]);
    return r;
}
__device__ __forceinline__ float blockSum(float v) {
    __shared__ float sh[8];
    v = warpSum(v);
    __syncthreads();
    if ((threadIdx.x & 31) == 0) sh[threadIdx.x >> 5] = v;
    __syncthreads();
    float r = 0.0f;
    int nw = blockDim.x >> 5;
    #pragma unroll
    for (int i = 0; i < 8; i++) if (i < nw) r += sh[i];
    return r;
}

// ---------------- dual softmax + blend -> fp16 ----------------
__global__ void __launch_bounds__(256)
softmax_blend(const float* __restrict__ mixed, const float* __restrict__ att,
              const float* __restrict__ w, h16* __restrict__ out)
{
    const long long base = (long long)blockIdx.x * T1;
    const int b = blockIdx.x >> 10;
    const int tid = threadIdx.x;
    float mv[8], av[8];
    float m1 = -1e30f, m2 = -1e30f;
    #pragma unroll
    for (int i = 0; i < 8; i++) {
        int c = tid + i * 256;
        mv[i] = mixed[base + c];
        av[i] = att[base + c] + w[(long long)b * T1 + c];
        m1 = fmaxf(m1, mv[i]);
        m2 = fmaxf(m2, av[i]);
    }
    m1 = blockMax(m1);
    m2 = blockMax(m2);
    float s1 = 0.f, s2 = 0.f;
    #pragma unroll
    for (int i = 0; i < 8; i++) {
        mv[i] = __expf(mv[i] - m1);
        av[i] = __expf(av[i] - m2);
        s1 += mv[i]; s2 += av[i];
    }
    s1 = blockSum(s1);
    s2 = blockSum(s2);
    const float r1 = TTMIX / s1, r2 = (1.0f - TTMIX) / s2;
    #pragma unroll
    for (int i = 0; i < 8; i++) {
        int c = tid + i * 256;
        out[base + c] = __float2half_rn(mv[i] * r1 + av[i] * r2);
    }
}

// ---------------- residual add + LayerNorm -> fp32 + fp16 --------------------
__global__ void __launch_bounds__(128)
add_ln(float* __restrict__ x, const float* __restrict__ slabs, int ns,
       long long sstride, const float* __restrict__ bias2,
       const float* __restrict__ g, const float* __restrict__ b,
       h16* __restrict__ xh)
{
    const long long base = (long long)blockIdx.x * D_;
    const int tid = threadIdx.x;
    float v[3];
    #pragma unroll
    for (int i = 0; i < 3; i++) {
        int c = tid + i * 128;
        float t = x[base + c];
        for (int s = 0; s < ns; s++) t += slabs[s * sstride + base + c];
        if (bias2) t += bias2[c];
        v[i] = t;
    }
    float s = v[0] + v[1] + v[2];
    s = blockSum(s);
    const float mean = s * (1.0f / D_);
    float q = 0.f;
    #pragma unroll
    for (int i = 0; i < 3; i++) { float d = v[i] - mean; q += d * d; }
    q = blockSum(q);
    const float rstd = rsqrtf(q * (1.0f / D_) + LN_EPS);
    #pragma unroll
    for (int i = 0; i < 3; i++) {
        int c = tid + i * 128;
        float o = (v[i] - mean) * rstd * g[c] + b[c];
        x[base + c] = o;
        xh[base + c] = __float2half_rn(o);
    }
}

// ---------------- host ----------------
#define SMEM_DYN (STAGES * STAGE_BYTES)
#define SYM(p, s) do { void* _t; cudaGetSymbolAddress(&_t, s); p = (decltype(p))_t; } while (0)

static void split(const float* in, h16* out, long long n, cudaStream_t st) {
    long long n4 = n / 4;
    cvt16<<<(unsigned)((n4 + 255) / 256), 256, 0, st>>>(in, out, n4);
}
static void gemm(const h16* A, const h16* B, const float* bias, float alpha,
                 int flags, float* Cf, h16* Ch,
                 int M, int N, int K, int batch,
                 long long sA, long long sB, long long sC, cudaStream_t st,
                 int kspl = 1, long long slabStride = 0) {
    dim3 g(N / 128, M / 128, batch * kspl);
    mma_gemm<<<g, 256, SMEM_DYN, st>>>(A, B, bias, alpha, flags, Cf, Ch,
                                       M, N, K, sA, sB, sC, kspl, slabStride);
}
static void transpose_split(const float* in, h16* out, int R, int C, int batch,
                            cudaStream_t st) {
    dim3 g(C / 32, R / 32, batch), b(32, 8);
    transpose16<<<g, b, 0, st>>>(in, out, R, C);
}

extern "C" void kernel_launch(void* const* d_in, const int* in_sizes, int n_in,
                              void* d_out, int out_size)
{
    (void)in_sizes; (void)n_in; (void)out_size;
    const float* tgt     = (const float*)d_in[0];
    const float* memory  = (const float*)d_in[1];
    const float* score_c = (const float*)d_in[2];
    const float* out_c   = (const float*)d_in[3];
    const float* Wq  = (const float*)d_in[4];
    const float* bq  = (const float*)d_in[5];
    const float* Wk  = (const float*)d_in[6];
    const float* Wv  = (const float*)d_in[8];
    const float* bv  = (const float*)d_in[9];
    const float* Wkn = (const float*)d_in[10];
    const float* bkn = (const float*)d_in[11];
    const float* Wun = (const float*)d_in[12];
    const float* bun = (const float*)d_in[13];
    const float* W1  = (const float*)d_in[14];
    const float* b1  = (const float*)d_in[15];
    const float* W2  = (const float*)d_in[16];
    const float* b2  = (const float*)d_in[17];
    const float* g1  = (const float*)d_in[18];
    const float* be1 = (const float*)d_in[19];
    const float* g2  = (const float*)d_in[20];
    const float* be2 = (const float*)d_in[21];

    float *x, *att, *mix, *m2slab, *z1slab, *y2slab, *zslab, *pvec, *wvec;
    SYM(x, g_x); SYM(att, g_att); SYM(mix, g_mix);
    SYM(m2slab, g_m2slab); SYM(z1slab, g_z1slab);
    SYM(y2slab, g_y2slab); SYM(zslab, g_zslab);
    SYM(pvec, g_pvec); SYM(wvec, g_wvec);
    h16 *xh,*qxh,*mh,*mth,*unh,*knh,*m2h,*blh,*hh,*oh,*sth;
    h16 *wqth,*wkth,*wqkth,*wvh,*wnh,*wuh,*w1h,*w2h;
    SYM(xh,g_xh); SYM(qxh,g_qxh); SYM(mh,g_mh); SYM(mth,g_mth);
    SYM(unh,g_unh); SYM(knh,g_knh); SYM(m2h,g_m2h); SYM(blh,g_blh);
    SYM(hh,g_hh); SYM(oh,g_oh); SYM(sth,g_sth);
    SYM(wqth,g_wqth); SYM(wkth,g_wkth); SYM(wqkth,g_wqkth);
    SYM(wvh,g_wvh); SYM(wnh,g_wnh); SYM(wuh,g_wuh);
    SYM(w1h,g_w1h); SYM(w2h,g_w2h);

    cudaFuncSetAttribute(mma_gemm, cudaFuncAttributeMaxDynamicSharedMemorySize, SMEM_DYN);

    // ---- streams/events (created once) ----
    static cudaStream_t s1 = nullptr, s2 = nullptr;
    static cudaEvent_t e0 = nullptr, s1done = nullptr;
    static cudaEvent_t ev_m2t[LY], ev_att[LY], ev_x[LY];
    if (!s1) {
        cudaStreamCreateWithFlags(&s1, cudaStreamNonBlocking);
        cudaStreamCreateWithFlags(&s2, cudaStreamNonBlocking);
        cudaEventCreateWithFlags(&e0, cudaEventDisableTiming);
        cudaEventCreateWithFlags(&s1done, cudaEventDisableTiming);
        for (int l = 0; l < LY; l++) {
            cudaEventCreateWithFlags(&ev_m2t[l], cudaEventDisableTiming);
            cudaEventCreateWithFlags(&ev_att[l], cudaEventDisableTiming);
            cudaEventCreateWithFlags(&ev_x[l], cudaEventDisableTiming);
        }
    }

    const float scale = 1.0f / sqrtf((float)D_);
    cudaStream_t s0 = 0;

    // ---- prologue (main stream) ----
    cudaMemcpyAsync(x, tgt, (size_t)NX * 4, cudaMemcpyDeviceToDevice, s0);
    split(tgt, xh, NX, s0);
    split(memory, mh, NMEM, s0);
    split(out_c, oh, NOC, s0);
    split(Wv, wvh, NWKT, s0);
    split(Wkn, wnh, NWQT, s0);
    split(Wun, wuh, NWQT, s0);
    split(W1, w1h, NW1, s0);
    split(W2, w2h, NW1, s0);
    transpose_split(memory, mth, T1, DK, BN, s0);
    transpose_split(Wq, wqth, D_, D_, LY, s0);
    transpose_split(Wk, wkth, D_, DK, LY, s0);
    gemm(wkth, wqth, nullptr, 1.f, 0, nullptr, wqkth,
         DK, D_, D_, LY, (long long)DK*D_, (long long)D_*D_, (long long)DK*D_, s0);
    for (int l = 0; l < LY; l++) {
        pvec_k<<<1, DK, 0, s0>>>(Wk + (long long)l*D_*DK, bq + (long long)l*D_, pvec);
        wvec_k<<<BN*T1/256, 256, 0, s0>>>(memory, pvec, wvec + (long long)l*BN*T1, scale);
    }
    cudaEventRecord(e0, s0);

    // ---- stream s1: x-independent precompute (all layers) ----
    cudaStreamWaitEvent(s1, e0, 0);
    for (int l = 0; l < LY; l++) {
        const long long oq = (long long)l * D_ * D_;
        // knoT_b = Wkn @ out_c_b^T + bkn (row bias): [D, TC]
        gemm(wnh + oq, oh + (long long)l*BN*TC*D_, bkn + (long long)l*D_, 1.f, 2,
             nullptr, knh, D_, TC, D_, BN, 0, (long long)TC*D_, (long long)D_*TC, s1);
        // score_c[l]^T -> sth [B, T1, TC]
        transpose_split(score_c + (long long)l*BN*TC*T1, sth, TC, T1, BN, s1);
        // M2T_b = scale * sth_b @ knoT_b^T : [T1, D], split-K=2
        gemm(sth, knh, nullptr, scale, 0, m2slab, nullptr,
             T1, D_, TC, BN, (long long)T1*TC, (long long)D_*TC, (long long)T1*D_,
             s1, 2, (long long)NM2);
        reduce16<<<(NM2/4 + 255)/256, 256, 0, s1>>>(
            m2slab, NM2/4, 2, m2h + (long long)l*NM2, NM2/4);
        cudaEventRecord(ev_m2t[l], s1);
    }
    cudaEventRecord(s1done, s1);

    // ---- main + s2 per-layer ----
    for (int l = 0; l < LY; l++) {
        const long long oq = (long long)l * D_ * D_;
        const long long ok = (long long)l * D_ * DK;
        const long long o1 = (long long)l * FF * D_;

        // s2: qx -> att (depends on current x)
        cudaStreamWaitEvent(s2, (l == 0) ? e0 : ev_x[l], 0);
        gemm(xh, wqkth + ok, nullptr, 1.f, 0, nullptr, qxh,
             BN*T_, DK, D_, 1, 0, 0, 0, s2);
        gemm(qxh, mh, nullptr, scale, 0, att, nullptr,
             T_, T1, DK, BN, (long long)T_*DK, (long long)T1*DK, (long long)T_*T1, s2);
        cudaEventRecord(ev_att[l], s2);

        // main: unk
        gemm(xh, wuh + oq, bun + (long long)l*D_, 1.f, 0, nullptr, unh,
             BN*T_, D_, D_, 1, 0, 0, 0, s0);
        // main: mixed (needs M2T[l])
        cudaStreamWaitEvent(s0, ev_m2t[l], 0);
        gemm(unh, m2h + (long long)l*NM2, nullptr, 1.f, 0, mix, nullptr,
             T_, T1, D_, BN, (long long)T_*D_, (long long)T1*D_, (long long)T_*T1, s0);
        // main: softmax blend (needs att)
        cudaStreamWaitEvent(s0, ev_att[l], 0);
        softmax_blend<<<BN*T_, 256, 0, s0>>>(mix, att, wvec + (long long)l*BN*T1, blh);
        // z1 = blended @ memT^T, split-K=4
        gemm(blh, mth, nullptr, 1.f, 0, z1slab, nullptr,
             T_, DK, T1, BN, (long long)T_*T1, (long long)DK*T1, (long long)T_*DK,
             s0, 4, (long long)NQX);
        reduce16<<<(NQX/4 + 255)/256, 256, 0, s0>>>(z1slab, NQX/4, 4, qxh, NQX/4);
        // z = z1 @ Wv^T, split-K=2 (bv added in add_ln)
        gemm(qxh, wvh + ok, nullptr, 1.f, 0, zslab, nullptr,
             BN*T_, D_, DK, 1, 0, 0, 0, s0, 2, (long long)NX);
        add_ln<<<BN*T_, 128, 0, s0>>>(x, zslab, 2, (long long)NX, bv + (long long)l*D_,
                                      g1 + (long long)l*D_, be1 + (long long)l*D_, xh);
        // h = relu(x @ W1^T + b1)
        gemm(xh, w1h + o1, b1 + (long long)l*FF, 1.f, 1, nullptr, hh,
             BN*T_, FF, D_, 1, 0, 0, 0, s0);
        // y2 = h @ W2^T, split-K=3 (b2 added in add_ln)
        gemm(hh, w2h + o1, nullptr, 1.f, 0, y2slab, nullptr,
             BN*T_, D_, FF, 1, 0, 0, 0, s0, 3, (long long)NX);
        add_ln<<<BN*T_, 128, 0, s0>>>(x, y2slab, 3, (long long)NX, b2 + (long long)l*D_,
                                      g2 + (long long)l*D_, be2 + (long long)l*D_, xh);
        if (l + 1 < LY) cudaEventRecord(ev_x[l + 1], s0);
    }

    cudaStreamWaitEvent(s0, s1done, 0);
    cudaMemcpyAsync(d_out, x, (size_t)NX * 4, cudaMemcpyDeviceToDevice, s0);
}